// round 5
// baseline (speedup 1.0000x reference)
#include <cuda_runtime.h>
#include <math.h>
#include <stdint.h>

// ---------------------------------------------------------------------------
// Problem constants
// ---------------------------------------------------------------------------
#define MTOK 32768
#define DMODEL 768
#define KVDIM 256
#define HIDDIM 2048
#define NB 2
#define NT 64
#define NS 256
#define NH 12
#define NKV 4

// ---------------------------------------------------------------------------
// Scratch (device globals; no allocation allowed)
// ---------------------------------------------------------------------------
__device__ float g_h [MTOK * DMODEL];
__device__ float g_q [MTOK * DMODEL];
__device__ float g_k [MTOK * KVDIM];
__device__ float g_v [MTOK * KVDIM];
__device__ float g_o [MTOK * DMODEL];
__device__ float g_x1[MTOK * DMODEL];
__device__ float g_h2[MTOK * DMODEL];
__device__ float g_u1[MTOK * HIDDIM];
__device__ float g_u2[MTOK * HIDDIM];
// transposed+tf32-converted weights  [N, K]
__device__ float g_wqT[DMODEL * DMODEL];
__device__ float g_wkT[KVDIM * DMODEL];
__device__ float g_wvT[KVDIM * DMODEL];
__device__ float g_woT[DMODEL * DMODEL];
__device__ float g_w1T[HIDDIM * DMODEL];
__device__ float g_w2T[HIDDIM * DMODEL];
__device__ float g_w3T[DMODEL * HIDDIM];

// ---------------------------------------------------------------------------
// helpers
// ---------------------------------------------------------------------------
__device__ __forceinline__ uint32_t f2tf32(float x) {
  uint32_t r;
  asm("cvt.rna.tf32.f32 %0, %1;" : "=r"(r) : "f"(x));
  return r;
}

__device__ __forceinline__ void mma_tf32(float* c, const uint32_t* a,
                                         const uint32_t* b) {
  asm volatile(
      "mma.sync.aligned.m16n8k8.row.col.f32.tf32.tf32.f32 "
      "{%0,%1,%2,%3}, {%4,%5,%6,%7}, {%8,%9}, {%0,%1,%2,%3};"
      : "+f"(c[0]), "+f"(c[1]), "+f"(c[2]), "+f"(c[3])
      : "r"(a[0]), "r"(a[1]), "r"(a[2]), "r"(a[3]), "r"(b[0]), "r"(b[1]));
}

__device__ __forceinline__ void cp_async16(uint32_t smem, const void* g) {
  asm volatile("cp.async.cg.shared.global [%0], [%1], 16;" ::"r"(smem),
               "l"(g));
}

// ---------------------------------------------------------------------------
// Weight transpose + tf32 convert: out[n*K + k] = tf32(in[k*N + n])
// K, N multiples of 32. 256 threads, 32x32 tiles.
// ---------------------------------------------------------------------------
__global__ __launch_bounds__(256) void transpose_tf32_kernel(
    const float* __restrict__ in, float* __restrict__ out, int K, int N) {
  __shared__ float tile[32][33];
  int n0 = blockIdx.x * 32;
  int k0 = blockIdx.y * 32;
  int tx = threadIdx.x & 31;
  int ty = threadIdx.x >> 5;  // 0..7
#pragma unroll
  for (int r = ty; r < 32; r += 8)
    tile[r][tx] = in[(size_t)(k0 + r) * N + n0 + tx];
  __syncthreads();
#pragma unroll
  for (int r = ty; r < 32; r += 8)
    out[(size_t)(n0 + r) * K + k0 + tx] = __uint_as_float(f2tf32(tile[tx][r]));
}

// ---------------------------------------------------------------------------
// Pipelined TF32 GEMM:  C[M,N] = A[M,K] @ Bt[N,K]^T  (+ R if non-null)
// A fp32 row-major; Bt already tf32-converted, row-major [N,K].
// 128x128 block tile, BK=32, 3-stage cp.async pipeline, 256 threads,
// 8 warps (4M x 2N), warp tile 32x64.  Dynamic smem = 108 KB.
// Stride-36 smem rows -> all fragment loads bank-conflict-free.
// ---------------------------------------------------------------------------
#define TSTRIDE 36
#define STAGEW (128 * TSTRIDE)  // words per stage per operand

__global__ __launch_bounds__(256, 1) void gemm_pipe_kernel(
    const float* __restrict__ A, const float* __restrict__ Bt,
    const float* __restrict__ R, float* __restrict__ C,
    int M, int N, int K) {
  extern __shared__ float sm[];
  float* Asm = sm;                       // 3 * STAGEW floats
  uint32_t* Bsm = (uint32_t*)(sm + 3 * STAGEW);

  const int tid = threadIdx.x;
  const int lane = tid & 31;
  const int warp = tid >> 5;
  const int wm = warp & 3;
  const int wn = warp >> 2;
  const int gid = lane >> 2;
  const int tin = lane & 3;
  const int bx = blockIdx.x;
  const int by = blockIdx.y;

  const float* Ag = A + (size_t)by * 128 * K;
  const float* Bg = Bt + (size_t)bx * 128 * K;

  const uint32_t a_base =
      (uint32_t)__cvta_generic_to_shared(Asm);
  const uint32_t b_base =
      (uint32_t)__cvta_generic_to_shared(Bsm);

  // staging indices: 1024 float4 per operand tile, 4 per thread
  const int srow = tid >> 1;                 // unused pattern below instead
  (void)srow;

  float acc[2][8][4];
#pragma unroll
  for (int mi = 0; mi < 2; mi++)
#pragma unroll
    for (int ni = 0; ni < 8; ni++)
#pragma unroll
      for (int f = 0; f < 4; f++) acc[mi][ni][f] = 0.f;

  const int ntiles = K >> 5;

  // stage issuer
  auto issue = [&](int st, int kt) {
#pragma unroll
    for (int r = 0; r < 4; r++) {
      int idx = tid + r * 256;
      int row = idx >> 3;
      int c4 = (idx & 7) << 2;
      cp_async16(a_base + (uint32_t)(st * STAGEW + row * TSTRIDE + c4) * 4,
                 Ag + (size_t)row * K + kt + c4);
      cp_async16(b_base + (uint32_t)(st * STAGEW + row * TSTRIDE + c4) * 4,
                 Bg + (size_t)row * K + kt + c4);
    }
  };

  // prologue: stages 0 and 1
  issue(0, 0);
  asm volatile("cp.async.commit_group;");
  issue(1, 32);
  asm volatile("cp.async.commit_group;");

  for (int it = 0; it < ntiles; ++it) {
    asm volatile("cp.async.wait_group 1;");
    __syncthreads();
    if (it + 2 < ntiles) issue((it + 2) % 3, (it + 2) * 32);
    asm volatile("cp.async.commit_group;");

    const float* As = Asm + (it % 3) * STAGEW;
    const uint32_t* Bs = Bsm + (it % 3) * STAGEW;
#pragma unroll
    for (int kt4 = 0; kt4 < 4; kt4++) {
      const int kc = kt4 * 8;
      uint32_t af[2][4];
#pragma unroll
      for (int mi = 0; mi < 2; mi++) {
        const float* p = As + (wm * 32 + mi * 16 + gid) * TSTRIDE + kc + tin;
        af[mi][0] = f2tf32(p[0]);
        af[mi][1] = f2tf32(p[8 * TSTRIDE]);
        af[mi][2] = f2tf32(p[4]);
        af[mi][3] = f2tf32(p[8 * TSTRIDE + 4]);
      }
      uint32_t bf[8][2];
#pragma unroll
      for (int ni = 0; ni < 8; ni++) {
        const uint32_t* p = Bs + (wn * 64 + ni * 8 + gid) * TSTRIDE + kc + tin;
        bf[ni][0] = p[0];
        bf[ni][1] = p[4];
      }
#pragma unroll
      for (int mi = 0; mi < 2; mi++)
#pragma unroll
        for (int ni = 0; ni < 8; ni++) mma_tf32(acc[mi][ni], af[mi], bf[ni]);
    }
    // no trailing barrier: next iteration's wait+barrier protects reuse
  }

  // epilogue
#pragma unroll
  for (int mi = 0; mi < 2; mi++) {
#pragma unroll
    for (int ni = 0; ni < 8; ni++) {
      int row = by * 128 + wm * 32 + mi * 16 + gid;
      int col = bx * 128 + wn * 64 + ni * 8 + (tin << 1);
      size_t o0 = (size_t)row * N + col;
      size_t o1 = (size_t)(row + 8) * N + col;
      float2 v0 = {acc[mi][ni][0], acc[mi][ni][1]};
      float2 v1 = {acc[mi][ni][2], acc[mi][ni][3]};
      if (R) {
        float2 r0 = *(const float2*)(R + o0);
        float2 r1 = *(const float2*)(R + o1);
        v0.x += r0.x; v0.y += r0.y;
        v1.x += r1.x; v1.y += r1.y;
      }
      *(float2*)(C + o0) = v0;
      *(float2*)(C + o1) = v1;
    }
  }
}

// ---------------------------------------------------------------------------
// Row RMSNorm over 768
// ---------------------------------------------------------------------------
__global__ __launch_bounds__(256) void rmsnorm_kernel(
    const float* __restrict__ x, const float* __restrict__ w,
    float* __restrict__ out) {
  const int row = blockIdx.x;
  const float* xr = x + (size_t)row * DMODEL;
  float* orow = out + (size_t)row * DMODEL;
  const int tid = threadIdx.x;
  float v0 = xr[tid];
  float v1 = xr[tid + 256];
  float v2 = xr[tid + 512];
  float s = v0 * v0 + v1 * v1 + v2 * v2;
#pragma unroll
  for (int off = 16; off > 0; off >>= 1)
    s += __shfl_xor_sync(0xffffffffu, s, off);
  __shared__ float ws[8];
  if ((tid & 31) == 0) ws[tid >> 5] = s;
  __syncthreads();
  float tot = ws[0] + ws[1] + ws[2] + ws[3] + ws[4] + ws[5] + ws[6] + ws[7];
  float rs = rsqrtf(tot * (1.0f / (float)DMODEL) + 1e-6f);
  orow[tid]       = v0 * rs * w[tid];
  orow[tid + 256] = v1 * rs * w[tid + 256];
  orow[tid + 512] = v2 * rs * w[tid + 512];
}

// ---------------------------------------------------------------------------
// Per-head RMSNorm over 64 (QK-norm), in-place
// ---------------------------------------------------------------------------
__global__ __launch_bounds__(256) void headnorm_kernel(
    float* __restrict__ x, const float* __restrict__ w, int nheads) {
  int head = blockIdx.x * 8 + (threadIdx.x >> 5);
  if (head >= nheads) return;
  int lane = threadIdx.x & 31;
  float* p = x + (size_t)head * 64;
  float a = p[lane];
  float b = p[lane + 32];
  float s = a * a + b * b;
#pragma unroll
  for (int off = 16; off > 0; off >>= 1)
    s += __shfl_xor_sync(0xffffffffu, s, off);
  float rs = rsqrtf(s * (1.0f / 64.0f) + 1e-6f);
  p[lane]      = a * rs * w[lane];
  p[lane + 32] = b * rs * w[lane + 32];
}

// ---------------------------------------------------------------------------
// Attention: one block per (b, s, h). Causal over T=64, HD=64.
// ---------------------------------------------------------------------------
__global__ __launch_bounds__(256) void attn_kernel(
    const float* __restrict__ q, const float* __restrict__ k,
    const float* __restrict__ v, float* __restrict__ o) {
  __shared__ float Qs[64][65];
  __shared__ float Ks[64][65];
  const int idx = blockIdx.x;
  const int h = idx % NH;
  const int s = (idx / NH) % NS;
  const int b = idx / (NH * NS);
  const int kvh = h / (NH / NKV);
  const int tid = threadIdx.x;

  for (int i = tid; i < 64 * 64; i += 256) {
    int t = i >> 6, d = i & 63;
    size_t tok = (size_t)((b * NT + t) * NS + s);
    Qs[t][d] = q[tok * DMODEL + h * 64 + d];
    Ks[t][d] = k[tok * KVDIM + kvh * 64 + d];
  }
  __syncthreads();

  const int row = tid >> 2;
  const int tj  = tid & 3;

  float lg[16];
#pragma unroll
  for (int jj = 0; jj < 16; jj++) {
    int j = tj * 16 + jj;
    float acc = 0.f;
#pragma unroll 8
    for (int d = 0; d < 64; d++) acc += Qs[row][d] * Ks[j][d];
    acc *= 0.125f;
    acc = 50.0f * tanhf(acc * 0.02f);
    lg[jj] = (j <= row) ? acc : -INFINITY;
  }

  float mx = lg[0];
#pragma unroll
  for (int jj = 1; jj < 16; jj++) mx = fmaxf(mx, lg[jj]);
  mx = fmaxf(mx, __shfl_xor_sync(0xffffffffu, mx, 1));
  mx = fmaxf(mx, __shfl_xor_sync(0xffffffffu, mx, 2));
  float sum = 0.f;
#pragma unroll
  for (int jj = 0; jj < 16; jj++) {
    float e = __expf(lg[jj] - mx);
    lg[jj] = e;
    sum += e;
  }
  sum += __shfl_xor_sync(0xffffffffu, sum, 1);
  sum += __shfl_xor_sync(0xffffffffu, sum, 2);
  float inv = 1.0f / sum;

  __syncthreads();
#pragma unroll
  for (int jj = 0; jj < 16; jj++) Qs[row][tj * 16 + jj] = lg[jj] * inv;
  for (int i = tid; i < 64 * 64; i += 256) {
    int t = i >> 6, d = i & 63;
    size_t tok = (size_t)((b * NT + t) * NS + s);
    Ks[t][d] = v[tok * KVDIM + kvh * 64 + d];
  }
  __syncthreads();

  float out[16];
#pragma unroll
  for (int dd = 0; dd < 16; dd++) out[dd] = 0.f;
  for (int j = 0; j < 64; j++) {
    float p = Qs[row][j];
#pragma unroll
    for (int dd = 0; dd < 16; dd++)
      out[dd] = fmaf(p, Ks[j][tj * 16 + dd], out[dd]);
  }
  size_t tok = (size_t)((b * NT + row) * NS + s);
#pragma unroll
  for (int dd = 0; dd < 16; dd++)
    o[tok * DMODEL + h * 64 + tj * 16 + dd] = out[dd];
}

// ---------------------------------------------------------------------------
// SwiGLU gate
// ---------------------------------------------------------------------------
__global__ __launch_bounds__(256) void swiglu_kernel(
    float* __restrict__ u1, const float* __restrict__ u2) {
  size_t i = (size_t)blockIdx.x * 256 + threadIdx.x;
  float4 a = ((const float4*)u1)[i];
  float4 b = ((const float4*)u2)[i];
  a.x = a.x / (1.f + __expf(-a.x)) * b.x;
  a.y = a.y / (1.f + __expf(-a.y)) * b.y;
  a.z = a.z / (1.f + __expf(-a.z)) * b.z;
  a.w = a.w / (1.f + __expf(-a.w)) * b.w;
  ((float4*)u1)[i] = a;
}

// ---------------------------------------------------------------------------
// Launch
// ---------------------------------------------------------------------------
extern "C" void kernel_launch(void* const* d_in, const int* in_sizes, int n_in,
                              void* d_out, int out_size) {
  const float* x  = (const float*)d_in[0];
  const float* n1 = (const float*)d_in[1];
  const float* n2 = (const float*)d_in[2];
  const float* qn = (const float*)d_in[3];
  const float* kn = (const float*)d_in[4];
  const float* wq = (const float*)d_in[5];
  const float* wk = (const float*)d_in[6];
  const float* wv = (const float*)d_in[7];
  const float* wo = (const float*)d_in[8];
  const float* w1 = (const float*)d_in[9];
  const float* w2 = (const float*)d_in[10];
  const float* w3 = (const float*)d_in[11];
  float* out = (float*)d_out;

  float *h, *q, *k, *v, *o, *x1, *h2, *u1, *u2;
  float *wqT, *wkT, *wvT, *woT, *w1T, *w2T, *w3T;
  cudaGetSymbolAddress((void**)&h,  g_h);
  cudaGetSymbolAddress((void**)&q,  g_q);
  cudaGetSymbolAddress((void**)&k,  g_k);
  cudaGetSymbolAddress((void**)&v,  g_v);
  cudaGetSymbolAddress((void**)&o,  g_o);
  cudaGetSymbolAddress((void**)&x1, g_x1);
  cudaGetSymbolAddress((void**)&h2, g_h2);
  cudaGetSymbolAddress((void**)&u1, g_u1);
  cudaGetSymbolAddress((void**)&u2, g_u2);
  cudaGetSymbolAddress((void**)&wqT, g_wqT);
  cudaGetSymbolAddress((void**)&wkT, g_wkT);
  cudaGetSymbolAddress((void**)&wvT, g_wvT);
  cudaGetSymbolAddress((void**)&woT, g_woT);
  cudaGetSymbolAddress((void**)&w1T, g_w1T);
  cudaGetSymbolAddress((void**)&w2T, g_w2T);
  cudaGetSymbolAddress((void**)&w3T, g_w3T);

  static bool attr_set = false;
  if (!attr_set) {
    cudaFuncSetAttribute(gemm_pipe_kernel,
                         cudaFuncAttributeMaxDynamicSharedMemorySize,
                         3 * 2 * STAGEW * 4);
    attr_set = true;
  }
  const int gsm = 3 * 2 * STAGEW * 4;  // 110592 bytes

  // 0. weight transpose + tf32 convert (cheap; once per launch)
  transpose_tf32_kernel<<<dim3(DMODEL / 32, DMODEL / 32), 256>>>(wq, wqT, DMODEL, DMODEL);
  transpose_tf32_kernel<<<dim3(KVDIM / 32, DMODEL / 32), 256>>>(wk, wkT, DMODEL, KVDIM);
  transpose_tf32_kernel<<<dim3(KVDIM / 32, DMODEL / 32), 256>>>(wv, wvT, DMODEL, KVDIM);
  transpose_tf32_kernel<<<dim3(DMODEL / 32, DMODEL / 32), 256>>>(wo, woT, DMODEL, DMODEL);
  transpose_tf32_kernel<<<dim3(HIDDIM / 32, DMODEL / 32), 256>>>(w1, w1T, DMODEL, HIDDIM);
  transpose_tf32_kernel<<<dim3(HIDDIM / 32, DMODEL / 32), 256>>>(w2, w2T, DMODEL, HIDDIM);
  transpose_tf32_kernel<<<dim3(DMODEL / 32, HIDDIM / 32), 256>>>(w3, w3T, HIDDIM, DMODEL);

  // 1. h = rmsnorm(x)
  rmsnorm_kernel<<<MTOK, 256>>>(x, n1, h);

  // 2-4. QKV projections
  {
    dim3 gq(DMODEL / 128, MTOK / 128);
    gemm_pipe_kernel<<<gq, 256, gsm>>>(h, wqT, nullptr, q, MTOK, DMODEL, DMODEL);
    dim3 gkv(KVDIM / 128, MTOK / 128);
    gemm_pipe_kernel<<<gkv, 256, gsm>>>(h, wkT, nullptr, k, MTOK, KVDIM, DMODEL);
    gemm_pipe_kernel<<<gkv, 256, gsm>>>(h, wvT, nullptr, v, MTOK, KVDIM, DMODEL);
  }

  // 5-6. QK-norm
  headnorm_kernel<<<(MTOK * NH) / 8, 256>>>(q, qn, MTOK * NH);
  headnorm_kernel<<<(MTOK * NKV) / 8, 256>>>(k, kn, MTOK * NKV);

  // 7. attention
  attn_kernel<<<NB * NS * NH, 256>>>(q, k, v, o);

  // 8. x1 = x + o @ wo
  {
    dim3 g(DMODEL / 128, MTOK / 128);
    gemm_pipe_kernel<<<g, 256, gsm>>>(o, woT, x, x1, MTOK, DMODEL, DMODEL);
  }

  // 9. h2 = rmsnorm(x1)
  rmsnorm_kernel<<<MTOK, 256>>>(x1, n2, h2);

  // 10-11. MLP up projections
  {
    dim3 g(HIDDIM / 128, MTOK / 128);
    gemm_pipe_kernel<<<g, 256, gsm>>>(h2, w1T, nullptr, u1, MTOK, HIDDIM, DMODEL);
    gemm_pipe_kernel<<<g, 256, gsm>>>(h2, w2T, nullptr, u2, MTOK, HIDDIM, DMODEL);
  }

  // 12. gate
  swiglu_kernel<<<(MTOK * HIDDIM) / (256 * 4), 256>>>(u1, u2);

  // 13. out = x1 + u1 @ w3
  {
    dim3 g(DMODEL / 128, MTOK / 128);
    gemm_pipe_kernel<<<g, 256, gsm>>>(u1, w3T, x1, out, MTOK, DMODEL, HIDDIM);
  }
}

// round 10
// speedup vs baseline: 1.5416x; 1.5416x over previous
#include <cuda_runtime.h>
#include <cuda_fp16.h>
#include <math.h>
#include <stdint.h>

// ---------------------------------------------------------------------------
// Problem constants
// ---------------------------------------------------------------------------
#define MTOK 32768
#define DMODEL 768
#define KVDIM 256
#define HIDDIM 2048
#define NB 2
#define NT 64
#define NS 256
#define NH 12
#define NKV 4

// ---------------------------------------------------------------------------
// Scratch (device globals; no allocation allowed)
// ---------------------------------------------------------------------------
__device__ __half g_h [MTOK * DMODEL];    // rmsnorm1(x) fp16
__device__ float  g_q [MTOK * DMODEL];
__device__ float  g_k [MTOK * KVDIM];
__device__ float  g_v [MTOK * KVDIM];
__device__ __half g_o [MTOK * DMODEL];    // attn out fp16
__device__ float  g_x1[MTOK * DMODEL];
__device__ __half g_h2[MTOK * DMODEL];    // rmsnorm2(x1) fp16
__device__ float  g_u1[MTOK * HIDDIM];
__device__ float  g_u2[MTOK * HIDDIM];
__device__ __half g_u1h[MTOK * HIDDIM];   // gated fp16
// transposed fp16 weights [N, K]
__device__ __half g_wqT[DMODEL * DMODEL];
__device__ __half g_wkT[KVDIM * DMODEL];
__device__ __half g_wvT[KVDIM * DMODEL];
__device__ __half g_woT[DMODEL * DMODEL];
__device__ __half g_w1T[HIDDIM * DMODEL];
__device__ __half g_w2T[HIDDIM * DMODEL];
__device__ __half g_w3T[DMODEL * HIDDIM];

// ---------------------------------------------------------------------------
// helpers
// ---------------------------------------------------------------------------
__device__ __forceinline__ void mma_f16(float* c, const uint32_t* a,
                                        const uint32_t* b) {
  asm volatile(
      "mma.sync.aligned.m16n8k16.row.col.f32.f16.f16.f32 "
      "{%0,%1,%2,%3}, {%4,%5,%6,%7}, {%8,%9}, {%0,%1,%2,%3};"
      : "+f"(c[0]), "+f"(c[1]), "+f"(c[2]), "+f"(c[3])
      : "r"(a[0]), "r"(a[1]), "r"(a[2]), "r"(a[3]), "r"(b[0]), "r"(b[1]));
}

__device__ __forceinline__ void cp_async16(uint32_t smem, const void* g) {
  asm volatile("cp.async.cg.shared.global [%0], [%1], 16;" ::"r"(smem), "l"(g));
}

// ---------------------------------------------------------------------------
// Weight transpose + fp16 convert: out[n*K + k] = (half)in[k*N + n]
// ---------------------------------------------------------------------------
__global__ __launch_bounds__(256) void transpose_f16_kernel(
    const float* __restrict__ in, __half* __restrict__ out, int K, int N) {
  __shared__ float tile[32][33];
  int n0 = blockIdx.x * 32;
  int k0 = blockIdx.y * 32;
  int tx = threadIdx.x & 31;
  int ty = threadIdx.x >> 5;
#pragma unroll
  for (int r = ty; r < 32; r += 8)
    tile[r][tx] = in[(size_t)(k0 + r) * N + n0 + tx];
  __syncthreads();
#pragma unroll
  for (int r = ty; r < 32; r += 8)
    out[(size_t)(n0 + r) * K + k0 + tx] = __float2half(tile[tx][r]);
}

// ---------------------------------------------------------------------------
// FP16 tensor-core GEMM: C[M,N] = A[M,K] @ Bt[N,K]^T (+ R if non-null)
// A, Bt fp16 row-major. 128x128 block tile, BK=32, 3-stage cp.async pipeline,
// 256 threads (8 warps, 4M x 2N), warp tile 32x64, mma m16n8k16.
// Smem rows padded to 20 half2 (80B) -> conflict-free fragment loads.
// ---------------------------------------------------------------------------
#define ROWH2 20                         // half2 per smem row (16 data + 4 pad)
#define TILEH2 (128 * ROWH2)             // half2 per operand tile
#define STAGEH2 (2 * TILEH2)             // A + B per stage
#define STAGES 3
#define GEMM_DSMEM (STAGES * STAGEH2 * 4)  // bytes (61440)

__global__ __launch_bounds__(256) void gemm_f16_kernel(
    const __half* __restrict__ A, const __half* __restrict__ Bt,
    const float* __restrict__ R, float* __restrict__ C,
    int M, int N, int K) {
  extern __shared__ uint32_t smh2[];   // half2 units

  const int tid = threadIdx.x;
  const int lane = tid & 31;
  const int warp = tid >> 5;
  const int wm = warp & 3;
  const int wn = warp >> 2;
  const int gid = lane >> 2;
  const int tin = lane & 3;
  const int bx = blockIdx.x;
  const int by = blockIdx.y;

  const __half* Ag = A + (size_t)by * 128 * K;
  const __half* Bg = Bt + (size_t)bx * 128 * K;
  const uint32_t sbase = (uint32_t)__cvta_generic_to_shared(smh2);

  float acc[2][8][4];
#pragma unroll
  for (int mi = 0; mi < 2; mi++)
#pragma unroll
    for (int ni = 0; ni < 8; ni++)
#pragma unroll
      for (int f = 0; f < 4; f++) acc[mi][ni][f] = 0.f;

  const int ntiles = K >> 5;

  // stage loader: tile 128 rows x 32 halves = 512 chunks of 8 halves (16B)
  auto issue = [&](int st, int kt) {
    const uint32_t ab = sbase + (uint32_t)(st * STAGEH2) * 4;
    const uint32_t bb = ab + TILEH2 * 4;
#pragma unroll
    for (int r = 0; r < 2; r++) {
      int c = tid + r * 256;            // 0..511
      int row = c >> 2;
      int cc = c & 3;                   // 8-half group
      cp_async16(ab + (uint32_t)(row * ROWH2 + cc * 4) * 4,
                 Ag + (size_t)row * K + kt + cc * 8);
      cp_async16(bb + (uint32_t)(row * ROWH2 + cc * 4) * 4,
                 Bg + (size_t)row * K + kt + cc * 8);
    }
  };

  issue(0, 0);
  asm volatile("cp.async.commit_group;");
  if (ntiles > 1) issue(1, 32);
  asm volatile("cp.async.commit_group;");

  for (int it = 0; it < ntiles; ++it) {
    asm volatile("cp.async.wait_group 1;");
    __syncthreads();
    if (it + 2 < ntiles) issue((it + 2) % 3, (it + 2) * 32);
    asm volatile("cp.async.commit_group;");

    const uint32_t* As = smh2 + (it % 3) * STAGEH2;
    const uint32_t* Bs = As + TILEH2;

#pragma unroll
    for (int ks = 0; ks < 2; ks++) {    // two k16 steps per BK=32
      const int kc = ks * 8;            // half2 offset
      uint32_t af[2][4];
#pragma unroll
      for (int mi = 0; mi < 2; mi++) {
        const uint32_t* p = As + (wm * 32 + mi * 16 + gid) * ROWH2 + kc + tin;
        af[mi][0] = p[0];
        af[mi][1] = p[8 * ROWH2];
        af[mi][2] = p[4];
        af[mi][3] = p[8 * ROWH2 + 4];
      }
      uint32_t bf[8][2];
#pragma unroll
      for (int ni = 0; ni < 8; ni++) {
        const uint32_t* p = Bs + (wn * 64 + ni * 8 + gid) * ROWH2 + kc + tin;
        bf[ni][0] = p[0];
        bf[ni][1] = p[4];
      }
#pragma unroll
      for (int mi = 0; mi < 2; mi++)
#pragma unroll
        for (int ni = 0; ni < 8; ni++) mma_f16(acc[mi][ni], af[mi], bf[ni]);
    }
  }

  // epilogue
#pragma unroll
  for (int mi = 0; mi < 2; mi++) {
#pragma unroll
    for (int ni = 0; ni < 8; ni++) {
      int row = by * 128 + wm * 32 + mi * 16 + gid;
      int col = bx * 128 + wn * 64 + ni * 8 + (tin << 1);
      size_t o0 = (size_t)row * N + col;
      size_t o1 = (size_t)(row + 8) * N + col;
      float2 v0 = {acc[mi][ni][0], acc[mi][ni][1]};
      float2 v1 = {acc[mi][ni][2], acc[mi][ni][3]};
      if (R) {
        float2 r0 = *(const float2*)(R + o0);
        float2 r1 = *(const float2*)(R + o1);
        v0.x += r0.x; v0.y += r0.y;
        v1.x += r1.x; v1.y += r1.y;
      }
      *(float2*)(C + o0) = v0;
      *(float2*)(C + o1) = v1;
    }
  }
}

// ---------------------------------------------------------------------------
// Row RMSNorm over 768 -> fp16 output
// ---------------------------------------------------------------------------
__global__ __launch_bounds__(256) void rmsnorm_kernel(
    const float* __restrict__ x, const float* __restrict__ w,
    __half* __restrict__ out) {
  const int row = blockIdx.x;
  const float* xr = x + (size_t)row * DMODEL;
  __half* orow = out + (size_t)row * DMODEL;
  const int tid = threadIdx.x;
  float v0 = xr[tid];
  float v1 = xr[tid + 256];
  float v2 = xr[tid + 512];
  float s = v0 * v0 + v1 * v1 + v2 * v2;
#pragma unroll
  for (int off = 16; off > 0; off >>= 1)
    s += __shfl_xor_sync(0xffffffffu, s, off);
  __shared__ float ws[8];
  if ((tid & 31) == 0) ws[tid >> 5] = s;
  __syncthreads();
  float tot = ws[0] + ws[1] + ws[2] + ws[3] + ws[4] + ws[5] + ws[6] + ws[7];
  float rs = rsqrtf(tot * (1.0f / (float)DMODEL) + 1e-6f);
  orow[tid]       = __float2half(v0 * rs * w[tid]);
  orow[tid + 256] = __float2half(v1 * rs * w[tid + 256]);
  orow[tid + 512] = __float2half(v2 * rs * w[tid + 512]);
}

// ---------------------------------------------------------------------------
// Per-head RMSNorm over 64 (QK-norm), fp32 in-place
// ---------------------------------------------------------------------------
__global__ __launch_bounds__(256) void headnorm_kernel(
    float* __restrict__ x, const float* __restrict__ w, int nheads) {
  int head = blockIdx.x * 8 + (threadIdx.x >> 5);
  if (head >= nheads) return;
  int lane = threadIdx.x & 31;
  float* p = x + (size_t)head * 64;
  float a = p[lane];
  float b = p[lane + 32];
  float s = a * a + b * b;
#pragma unroll
  for (int off = 16; off > 0; off >>= 1)
    s += __shfl_xor_sync(0xffffffffu, s, off);
  float rs = rsqrtf(s * (1.0f / 64.0f) + 1e-6f);
  p[lane]      = a * rs * w[lane];
  p[lane + 32] = b * rs * w[lane + 32];
}

// ---------------------------------------------------------------------------
// Attention: one block per (b, s, h). Causal over T=64, HD=64. fp16 output.
// ---------------------------------------------------------------------------
__global__ __launch_bounds__(256) void attn_kernel(
    const float* __restrict__ q, const float* __restrict__ k,
    const float* __restrict__ v, __half* __restrict__ o) {
  __shared__ float Qs[64][65];
  __shared__ float Ks[64][65];
  const int idx = blockIdx.x;
  const int h = idx % NH;
  const int s = (idx / NH) % NS;
  const int b = idx / (NH * NS);
  const int kvh = h / (NH / NKV);
  const int tid = threadIdx.x;

  for (int i = tid; i < 64 * 64; i += 256) {
    int t = i >> 6, d = i & 63;
    size_t tok = (size_t)((b * NT + t) * NS + s);
    Qs[t][d] = q[tok * DMODEL + h * 64 + d];
    Ks[t][d] = k[tok * KVDIM + kvh * 64 + d];
  }
  __syncthreads();

  const int row = tid >> 2;
  const int tj  = tid & 3;

  float lg[16];
#pragma unroll
  for (int jj = 0; jj < 16; jj++) {
    int j = tj * 16 + jj;
    float acc = 0.f;
#pragma unroll 8
    for (int d = 0; d < 64; d++) acc += Qs[row][d] * Ks[j][d];
    acc *= 0.125f;
    acc = 50.0f * tanhf(acc * 0.02f);
    lg[jj] = (j <= row) ? acc : -INFINITY;
  }

  float mx = lg[0];
#pragma unroll
  for (int jj = 1; jj < 16; jj++) mx = fmaxf(mx, lg[jj]);
  mx = fmaxf(mx, __shfl_xor_sync(0xffffffffu, mx, 1));
  mx = fmaxf(mx, __shfl_xor_sync(0xffffffffu, mx, 2));
  float sum = 0.f;
#pragma unroll
  for (int jj = 0; jj < 16; jj++) {
    float e = __expf(lg[jj] - mx);
    lg[jj] = e;
    sum += e;
  }
  sum += __shfl_xor_sync(0xffffffffu, sum, 1);
  sum += __shfl_xor_sync(0xffffffffu, sum, 2);
  float inv = 1.0f / sum;

  __syncthreads();
#pragma unroll
  for (int jj = 0; jj < 16; jj++) Qs[row][tj * 16 + jj] = lg[jj] * inv;
  for (int i = tid; i < 64 * 64; i += 256) {
    int t = i >> 6, d = i & 63;
    size_t tok = (size_t)((b * NT + t) * NS + s);
    Ks[t][d] = v[tok * KVDIM + kvh * 64 + d];
  }
  __syncthreads();

  float out[16];
#pragma unroll
  for (int dd = 0; dd < 16; dd++) out[dd] = 0.f;
  for (int j = 0; j < 64; j++) {
    float p = Qs[row][j];
#pragma unroll
    for (int dd = 0; dd < 16; dd++)
      out[dd] = fmaf(p, Ks[j][tj * 16 + dd], out[dd]);
  }
  size_t tok = (size_t)((b * NT + row) * NS + s);
#pragma unroll
  for (int dd = 0; dd < 16; dd++)
    o[tok * DMODEL + h * 64 + tj * 16 + dd] = __float2half(out[dd]);
}

// ---------------------------------------------------------------------------
// SwiGLU gate -> fp16: u1h = (half)(silu(u1) * u2)
// ---------------------------------------------------------------------------
__global__ __launch_bounds__(256) void swiglu_kernel(
    const float* __restrict__ u1, const float* __restrict__ u2,
    __half* __restrict__ u1h) {
  size_t i = (size_t)blockIdx.x * 256 + threadIdx.x;
  float4 a = ((const float4*)u1)[i];
  float4 b = ((const float4*)u2)[i];
  __half2* dst = (__half2*)u1h;
  float r0 = a.x / (1.f + __expf(-a.x)) * b.x;
  float r1 = a.y / (1.f + __expf(-a.y)) * b.y;
  float r2 = a.z / (1.f + __expf(-a.z)) * b.z;
  float r3 = a.w / (1.f + __expf(-a.w)) * b.w;
  dst[i * 2]     = __floats2half2_rn(r0, r1);
  dst[i * 2 + 1] = __floats2half2_rn(r2, r3);
}

// ---------------------------------------------------------------------------
// Launch
// ---------------------------------------------------------------------------
extern "C" void kernel_launch(void* const* d_in, const int* in_sizes, int n_in,
                              void* d_out, int out_size) {
  const float* x  = (const float*)d_in[0];
  const float* n1 = (const float*)d_in[1];
  const float* n2 = (const float*)d_in[2];
  const float* qn = (const float*)d_in[3];
  const float* kn = (const float*)d_in[4];
  const float* wq = (const float*)d_in[5];
  const float* wk = (const float*)d_in[6];
  const float* wv = (const float*)d_in[7];
  const float* wo = (const float*)d_in[8];
  const float* w1 = (const float*)d_in[9];
  const float* w2 = (const float*)d_in[10];
  const float* w3 = (const float*)d_in[11];
  float* out = (float*)d_out;

  __half *h, *o, *h2, *u1h;
  float *q, *k, *v, *x1, *u1, *u2;
  __half *wqT, *wkT, *wvT, *woT, *w1T, *w2T, *w3T;
  cudaGetSymbolAddress((void**)&h,   g_h);
  cudaGetSymbolAddress((void**)&q,   g_q);
  cudaGetSymbolAddress((void**)&k,   g_k);
  cudaGetSymbolAddress((void**)&v,   g_v);
  cudaGetSymbolAddress((void**)&o,   g_o);
  cudaGetSymbolAddress((void**)&x1,  g_x1);
  cudaGetSymbolAddress((void**)&h2,  g_h2);
  cudaGetSymbolAddress((void**)&u1,  g_u1);
  cudaGetSymbolAddress((void**)&u2,  g_u2);
  cudaGetSymbolAddress((void**)&u1h, g_u1h);
  cudaGetSymbolAddress((void**)&wqT, g_wqT);
  cudaGetSymbolAddress((void**)&wkT, g_wkT);
  cudaGetSymbolAddress((void**)&wvT, g_wvT);
  cudaGetSymbolAddress((void**)&woT, g_woT);
  cudaGetSymbolAddress((void**)&w1T, g_w1T);
  cudaGetSymbolAddress((void**)&w2T, g_w2T);
  cudaGetSymbolAddress((void**)&w3T, g_w3T);

  static bool attr_set = false;
  if (!attr_set) {
    cudaFuncSetAttribute(gemm_f16_kernel,
                         cudaFuncAttributeMaxDynamicSharedMemorySize,
                         GEMM_DSMEM);
    attr_set = true;
  }

  // 0. weight transpose + fp16 convert
  transpose_f16_kernel<<<dim3(DMODEL / 32, DMODEL / 32), 256>>>(wq, wqT, DMODEL, DMODEL);
  transpose_f16_kernel<<<dim3(KVDIM / 32, DMODEL / 32), 256>>>(wk, wkT, DMODEL, KVDIM);
  transpose_f16_kernel<<<dim3(KVDIM / 32, DMODEL / 32), 256>>>(wv, wvT, DMODEL, KVDIM);
  transpose_f16_kernel<<<dim3(DMODEL / 32, DMODEL / 32), 256>>>(wo, woT, DMODEL, DMODEL);
  transpose_f16_kernel<<<dim3(HIDDIM / 32, DMODEL / 32), 256>>>(w1, w1T, DMODEL, HIDDIM);
  transpose_f16_kernel<<<dim3(HIDDIM / 32, DMODEL / 32), 256>>>(w2, w2T, DMODEL, HIDDIM);
  transpose_f16_kernel<<<dim3(DMODEL / 32, HIDDIM / 32), 256>>>(w3, w3T, HIDDIM, DMODEL);

  // 1. h = rmsnorm(x)  (fp16)
  rmsnorm_kernel<<<MTOK, 256>>>(x, n1, h);

  // 2-4. QKV projections
  gemm_f16_kernel<<<dim3(DMODEL / 128, MTOK / 128), 256, GEMM_DSMEM>>>(
      h, wqT, nullptr, q, MTOK, DMODEL, DMODEL);
  gemm_f16_kernel<<<dim3(KVDIM / 128, MTOK / 128), 256, GEMM_DSMEM>>>(
      h, wkT, nullptr, k, MTOK, KVDIM, DMODEL);
  gemm_f16_kernel<<<dim3(KVDIM / 128, MTOK / 128), 256, GEMM_DSMEM>>>(
      h, wvT, nullptr, v, MTOK, KVDIM, DMODEL);

  // 5-6. QK-norm
  headnorm_kernel<<<(MTOK * NH) / 8, 256>>>(q, qn, MTOK * NH);
  headnorm_kernel<<<(MTOK * NKV) / 8, 256>>>(k, kn, MTOK * NKV);

  // 7. attention (fp16 out)
  attn_kernel<<<NB * NS * NH, 256>>>(q, k, v, o);

  // 8. x1 = x + o @ wo
  gemm_f16_kernel<<<dim3(DMODEL / 128, MTOK / 128), 256, GEMM_DSMEM>>>(
      o, woT, x, x1, MTOK, DMODEL, DMODEL);

  // 9. h2 = rmsnorm(x1) (fp16)
  rmsnorm_kernel<<<MTOK, 256>>>(x1, n2, h2);

  // 10-11. MLP up projections
  gemm_f16_kernel<<<dim3(HIDDIM / 128, MTOK / 128), 256, GEMM_DSMEM>>>(
      h2, w1T, nullptr, u1, MTOK, HIDDIM, DMODEL);
  gemm_f16_kernel<<<dim3(HIDDIM / 128, MTOK / 128), 256, GEMM_DSMEM>>>(
      h2, w2T, nullptr, u2, MTOK, HIDDIM, DMODEL);

  // 12. gate (fp16 out)
  swiglu_kernel<<<(MTOK * HIDDIM) / (256 * 4), 256>>>(u1, u2, u1h);

  // 13. out = x1 + u1h @ w3
  gemm_f16_kernel<<<dim3(DMODEL / 128, MTOK / 128), 256, GEMM_DSMEM>>>(
      u1h, w3T, x1, out, MTOK, DMODEL, HIDDIM);
}

// round 14
// speedup vs baseline: 1.5990x; 1.0373x over previous
#include <cuda_runtime.h>
#include <cuda_fp16.h>
#include <math.h>
#include <stdint.h>

// ---------------------------------------------------------------------------
// Problem constants
// ---------------------------------------------------------------------------
#define MTOK 32768
#define DMODEL 768
#define KVDIM 256
#define QKVDIM 1280   // 768 + 256 + 256
#define HIDDIM 2048
#define HID2 4096     // w1 | w2 merged
#define NB 2
#define NT 64
#define NS 256
#define NH 12
#define NKV 4

// ---------------------------------------------------------------------------
// Scratch (device globals; no allocation allowed)
// ---------------------------------------------------------------------------
__device__ __half g_h  [MTOK * DMODEL];    // rmsnorm1(x) fp16
__device__ float  g_qkv[MTOK * QKVDIM];    // q|k|v fp32
__device__ __half g_o  [MTOK * DMODEL];    // attn out fp16
__device__ float  g_x1 [MTOK * DMODEL];
__device__ __half g_h2 [MTOK * DMODEL];    // rmsnorm2(x1) fp16
__device__ float  g_u12[MTOK * HID2];      // u1|u2 fp32
__device__ __half g_u1h[MTOK * HIDDIM];    // gated fp16
// transposed fp16 weights [N, K]
__device__ __half g_wqkvT[QKVDIM * DMODEL];  // wq^T rows 0-767, wk^T 768-1023, wv^T 1024-1279
__device__ __half g_woT  [DMODEL * DMODEL];
__device__ __half g_w12T [HID2 * DMODEL];    // w1^T rows 0-2047, w2^T 2048-4095
__device__ __half g_w3T  [DMODEL * HIDDIM];

// ---------------------------------------------------------------------------
// helpers
// ---------------------------------------------------------------------------
__device__ __forceinline__ void mma_f16(float* c, const uint32_t* a,
                                        const uint32_t* b) {
  asm volatile(
      "mma.sync.aligned.m16n8k16.row.col.f32.f16.f16.f32 "
      "{%0,%1,%2,%3}, {%4,%5,%6,%7}, {%8,%9}, {%0,%1,%2,%3};"
      : "+f"(c[0]), "+f"(c[1]), "+f"(c[2]), "+f"(c[3])
      : "r"(a[0]), "r"(a[1]), "r"(a[2]), "r"(a[3]), "r"(b[0]), "r"(b[1]));
}

__device__ __forceinline__ void cp_async16(uint32_t smem, const void* g) {
  asm volatile("cp.async.cg.shared.global [%0], [%1], 16;" ::"r"(smem), "l"(g));
}

__device__ __forceinline__ void ldsm_x4(uint32_t* r, uint32_t addr) {
  asm volatile(
      "ldmatrix.sync.aligned.m8n8.x4.shared.b16 {%0,%1,%2,%3}, [%4];"
      : "=r"(r[0]), "=r"(r[1]), "=r"(r[2]), "=r"(r[3])
      : "r"(addr));
}

// ---------------------------------------------------------------------------
// Weight transpose + fp16 convert: out[n*K + k] = (half)in[k*N + n]
// (out may point into a larger merged [Ntot, K] buffer at a row offset)
// ---------------------------------------------------------------------------
__global__ __launch_bounds__(256) void transpose_f16_kernel(
    const float* __restrict__ in, __half* __restrict__ out, int K, int N) {
  __shared__ float tile[32][33];
  int n0 = blockIdx.x * 32;
  int k0 = blockIdx.y * 32;
  int tx = threadIdx.x & 31;
  int ty = threadIdx.x >> 5;
#pragma unroll
  for (int r = ty; r < 32; r += 8)
    tile[r][tx] = in[(size_t)(k0 + r) * N + n0 + tx];
  __syncthreads();
#pragma unroll
  for (int r = ty; r < 32; r += 8)
    out[(size_t)(n0 + r) * K + k0 + tx] = __float2half(tile[tx][r]);
}

// ---------------------------------------------------------------------------
// FP16 tensor-core GEMM with ldmatrix: C[M,N] = A[M,K] @ Bt[N,K]^T (+R)
// 128x128 block tile, BK=32, 3-stage cp.async pipeline, 256 threads
// (8 warps, 4M x 2N), warp tile 32x64, mma m16n8k16, ldmatrix.x4 fragments.
// Smem rows 20 half2 (80B) -> ldmatrix phases conflict-free.
// ---------------------------------------------------------------------------
#define ROWH2 20
#define TILEH2 (128 * ROWH2)
#define STAGEH2 (2 * TILEH2)
#define STAGES 3
#define GEMM_DSMEM (STAGES * STAGEH2 * 4)  // 61440 bytes

__global__ __launch_bounds__(256) void gemm_f16_kernel(
    const __half* __restrict__ A, const __half* __restrict__ Bt,
    const float* __restrict__ R, float* __restrict__ C,
    int M, int N, int K) {
  extern __shared__ uint32_t smh2[];

  const int tid = threadIdx.x;
  const int lane = tid & 31;
  const int warp = tid >> 5;
  const int wm = warp & 3;
  const int wn = warp >> 2;
  const int gid = lane >> 2;
  const int tin = lane & 3;
  const int grp = lane >> 3;     // ldmatrix quadrant 0..3
  const int l8 = lane & 7;
  const int bx = blockIdx.x;
  const int by = blockIdx.y;

  const __half* Ag = A + (size_t)by * 128 * K;
  const __half* Bg = Bt + (size_t)bx * 128 * K;
  const uint32_t sbase = (uint32_t)__cvta_generic_to_shared(smh2);

  // ldmatrix lane-address components (bytes, within a stage)
  // A: quadrants (grp&1)->row+8, (grp>>1)->k+16B
  const uint32_t a_lane_off =
      (uint32_t)((wm * 32 + ((grp & 1) << 3) + l8) * 80 + ((grp >> 1) << 4));
  // B: quadrants (grp>>1)->row+8, (grp&1)->k+16B
  const uint32_t b_lane_off =
      (uint32_t)((wn * 64 + ((grp >> 1) << 3) + l8) * 80 + ((grp & 1) << 4)) +
      (uint32_t)TILEH2 * 4;

  float acc[2][8][4];
#pragma unroll
  for (int mi = 0; mi < 2; mi++)
#pragma unroll
    for (int ni = 0; ni < 8; ni++)
#pragma unroll
      for (int f = 0; f < 4; f++) acc[mi][ni][f] = 0.f;

  const int ntiles = K >> 5;

  auto issue = [&](int st, int kt) {
    const uint32_t ab = sbase + (uint32_t)(st * STAGEH2) * 4;
    const uint32_t bb = ab + TILEH2 * 4;
#pragma unroll
    for (int r = 0; r < 2; r++) {
      int c = tid + r * 256;
      int row = c >> 2;
      int cc = c & 3;
      cp_async16(ab + (uint32_t)(row * ROWH2 + cc * 4) * 4,
                 Ag + (size_t)row * K + kt + cc * 8);
      cp_async16(bb + (uint32_t)(row * ROWH2 + cc * 4) * 4,
                 Bg + (size_t)row * K + kt + cc * 8);
    }
  };

  issue(0, 0);
  asm volatile("cp.async.commit_group;");
  if (ntiles > 1) issue(1, 32);
  asm volatile("cp.async.commit_group;");

  for (int it = 0; it < ntiles; ++it) {
    asm volatile("cp.async.wait_group 1;");
    __syncthreads();
    if (it + 2 < ntiles) issue((it + 2) % 3, (it + 2) * 32);
    asm volatile("cp.async.commit_group;");

    const uint32_t stage_byte = sbase + (uint32_t)((it % 3) * STAGEH2) * 4;

#pragma unroll
    for (int ks = 0; ks < 2; ks++) {
      const uint32_t kb = ks * 32;  // byte offset of k16 step
      uint32_t af[2][4];
#pragma unroll
      for (int mi = 0; mi < 2; mi++)
        ldsm_x4(af[mi], stage_byte + a_lane_off + (uint32_t)(mi * 16 * 80) + kb);
      uint32_t bf[8][2];
#pragma unroll
      for (int p = 0; p < 4; p++) {
        uint32_t t[4];
        ldsm_x4(t, stage_byte + b_lane_off + (uint32_t)(p * 16 * 80) + kb);
        bf[2 * p][0] = t[0];
        bf[2 * p][1] = t[1];
        bf[2 * p + 1][0] = t[2];
        bf[2 * p + 1][1] = t[3];
      }
#pragma unroll
      for (int mi = 0; mi < 2; mi++)
#pragma unroll
        for (int ni = 0; ni < 8; ni++) mma_f16(acc[mi][ni], af[mi], bf[ni]);
    }
  }

  // epilogue
#pragma unroll
  for (int mi = 0; mi < 2; mi++) {
#pragma unroll
    for (int ni = 0; ni < 8; ni++) {
      int row = by * 128 + wm * 32 + mi * 16 + gid;
      int col = bx * 128 + wn * 64 + ni * 8 + (tin << 1);
      size_t o0 = (size_t)row * N + col;
      size_t o1 = (size_t)(row + 8) * N + col;
      float2 v0 = {acc[mi][ni][0], acc[mi][ni][1]};
      float2 v1 = {acc[mi][ni][2], acc[mi][ni][3]};
      if (R) {
        float2 r0 = *(const float2*)(R + o0);
        float2 r1 = *(const float2*)(R + o1);
        v0.x += r0.x; v0.y += r0.y;
        v1.x += r1.x; v1.y += r1.y;
      }
      *(float2*)(C + o0) = v0;
      *(float2*)(C + o1) = v1;
    }
  }
}

// ---------------------------------------------------------------------------
// Row RMSNorm over 768 -> fp16 output
// ---------------------------------------------------------------------------
__global__ __launch_bounds__(256) void rmsnorm_kernel(
    const float* __restrict__ x, const float* __restrict__ w,
    __half* __restrict__ out) {
  const int row = blockIdx.x;
  const float* xr = x + (size_t)row * DMODEL;
  __half* orow = out + (size_t)row * DMODEL;
  const int tid = threadIdx.x;
  float v0 = xr[tid];
  float v1 = xr[tid + 256];
  float v2 = xr[tid + 512];
  float s = v0 * v0 + v1 * v1 + v2 * v2;
#pragma unroll
  for (int off = 16; off > 0; off >>= 1)
    s += __shfl_xor_sync(0xffffffffu, s, off);
  __shared__ float ws[8];
  if ((tid & 31) == 0) ws[tid >> 5] = s;
  __syncthreads();
  float tot = ws[0] + ws[1] + ws[2] + ws[3] + ws[4] + ws[5] + ws[6] + ws[7];
  float rs = rsqrtf(tot * (1.0f / (float)DMODEL) + 1e-6f);
  orow[tid]       = __float2half(v0 * rs * w[tid]);
  orow[tid + 256] = __float2half(v1 * rs * w[tid + 256]);
  orow[tid + 512] = __float2half(v2 * rs * w[tid + 512]);
}

// ---------------------------------------------------------------------------
// Attention with fused QK-norm: one block per (b, s, h).
// q/k/v read from merged qkv buffer [tok][1280]; fp16 output.
// ---------------------------------------------------------------------------
__global__ __launch_bounds__(256) void attn_kernel(
    const float* __restrict__ qkv, const float* __restrict__ qn,
    const float* __restrict__ kn, __half* __restrict__ o) {
  __shared__ float Qs[64][65];
  __shared__ float Ks[64][65];
  const int idx = blockIdx.x;
  const int h = idx % NH;
  const int s = (idx / NH) % NS;
  const int b = idx / (NH * NS);
  const int kvh = h / (NH / NKV);
  const int tid = threadIdx.x;

  for (int i = tid; i < 64 * 64; i += 256) {
    int t = i >> 6, d = i & 63;
    size_t tok = (size_t)((b * NT + t) * NS + s);
    Qs[t][d] = qkv[tok * QKVDIM + h * 64 + d];
    Ks[t][d] = qkv[tok * QKVDIM + DMODEL + kvh * 64 + d];
  }
  __syncthreads();

  const int row = tid >> 2;
  const int tj  = tid & 3;

  // fused QK RMSNorm (per row of 64)
  {
    float sq = 0.f, sk = 0.f;
#pragma unroll
    for (int jj = 0; jj < 16; jj++) {
      float a = Qs[row][tj * 16 + jj];
      float c = Ks[row][tj * 16 + jj];
      sq += a * a;
      sk += c * c;
    }
    sq += __shfl_xor_sync(0xffffffffu, sq, 1);
    sq += __shfl_xor_sync(0xffffffffu, sq, 2);
    sk += __shfl_xor_sync(0xffffffffu, sk, 1);
    sk += __shfl_xor_sync(0xffffffffu, sk, 2);
    float rq = rsqrtf(sq * (1.0f / 64.0f) + 1e-6f);
    float rk = rsqrtf(sk * (1.0f / 64.0f) + 1e-6f);
#pragma unroll
    for (int jj = 0; jj < 16; jj++) {
      int d = tj * 16 + jj;
      Qs[row][d] *= rq * qn[d];
      Ks[row][d] *= rk * kn[d];
    }
  }
  __syncthreads();

  float lg[16];
#pragma unroll
  for (int jj = 0; jj < 16; jj++) {
    int j = tj * 16 + jj;
    float acc = 0.f;
#pragma unroll 8
    for (int d = 0; d < 64; d++) acc += Qs[row][d] * Ks[j][d];
    acc *= 0.125f;
    acc = 50.0f * tanhf(acc * 0.02f);
    lg[jj] = (j <= row) ? acc : -INFINITY;
  }

  float mx = lg[0];
#pragma unroll
  for (int jj = 1; jj < 16; jj++) mx = fmaxf(mx, lg[jj]);
  mx = fmaxf(mx, __shfl_xor_sync(0xffffffffu, mx, 1));
  mx = fmaxf(mx, __shfl_xor_sync(0xffffffffu, mx, 2));
  float sum = 0.f;
#pragma unroll
  for (int jj = 0; jj < 16; jj++) {
    float e = __expf(lg[jj] - mx);
    lg[jj] = e;
    sum += e;
  }
  sum += __shfl_xor_sync(0xffffffffu, sum, 1);
  sum += __shfl_xor_sync(0xffffffffu, sum, 2);
  float inv = 1.0f / sum;

  __syncthreads();
#pragma unroll
  for (int jj = 0; jj < 16; jj++) Qs[row][tj * 16 + jj] = lg[jj] * inv;
  for (int i = tid; i < 64 * 64; i += 256) {
    int t = i >> 6, d = i & 63;
    size_t tok = (size_t)((b * NT + t) * NS + s);
    Ks[t][d] = qkv[tok * QKVDIM + DMODEL + KVDIM + kvh * 64 + d];
  }
  __syncthreads();

  float out[16];
#pragma unroll
  for (int dd = 0; dd < 16; dd++) out[dd] = 0.f;
  for (int j = 0; j < 64; j++) {
    float p = Qs[row][j];
#pragma unroll
    for (int dd = 0; dd < 16; dd++)
      out[dd] = fmaf(p, Ks[j][tj * 16 + dd], out[dd]);
  }
  size_t tok = (size_t)((b * NT + row) * NS + s);
#pragma unroll
  for (int dd = 0; dd < 16; dd++)
    o[tok * DMODEL + h * 64 + tj * 16 + dd] = __float2half(out[dd]);
}

// ---------------------------------------------------------------------------
// SwiGLU gate on merged buffer: u1h = (half)(silu(u12[:, :2048]) * u12[:, 2048:])
// ---------------------------------------------------------------------------
__global__ __launch_bounds__(256) void swiglu_kernel(
    const float* __restrict__ u12, __half* __restrict__ u1h) {
  size_t idx = (size_t)blockIdx.x * 256 + threadIdx.x;
  size_t c4 = idx * 4;
  size_t r = c4 >> 11;            // / 2048
  size_t c = c4 & 2047;
  float4 a = *(const float4*)(u12 + r * HID2 + c);
  float4 b = *(const float4*)(u12 + r * HID2 + HIDDIM + c);
  float r0 = a.x / (1.f + __expf(-a.x)) * b.x;
  float r1 = a.y / (1.f + __expf(-a.y)) * b.y;
  float r2 = a.z / (1.f + __expf(-a.z)) * b.z;
  float r3 = a.w / (1.f + __expf(-a.w)) * b.w;
  __half2* dst = (__half2*)(u1h + r * HIDDIM + c);
  dst[0] = __floats2half2_rn(r0, r1);
  dst[1] = __floats2half2_rn(r2, r3);
}

// ---------------------------------------------------------------------------
// Launch
// ---------------------------------------------------------------------------
extern "C" void kernel_launch(void* const* d_in, const int* in_sizes, int n_in,
                              void* d_out, int out_size) {
  const float* x  = (const float*)d_in[0];
  const float* n1 = (const float*)d_in[1];
  const float* n2 = (const float*)d_in[2];
  const float* qn = (const float*)d_in[3];
  const float* kn = (const float*)d_in[4];
  const float* wq = (const float*)d_in[5];
  const float* wk = (const float*)d_in[6];
  const float* wv = (const float*)d_in[7];
  const float* wo = (const float*)d_in[8];
  const float* w1 = (const float*)d_in[9];
  const float* w2 = (const float*)d_in[10];
  const float* w3 = (const float*)d_in[11];
  float* out = (float*)d_out;

  __half *h, *o, *h2, *u1h;
  float *qkv, *x1, *u12;
  __half *wqkvT, *woT, *w12T, *w3T;
  cudaGetSymbolAddress((void**)&h,     g_h);
  cudaGetSymbolAddress((void**)&qkv,   g_qkv);
  cudaGetSymbolAddress((void**)&o,     g_o);
  cudaGetSymbolAddress((void**)&x1,    g_x1);
  cudaGetSymbolAddress((void**)&h2,    g_h2);
  cudaGetSymbolAddress((void**)&u12,   g_u12);
  cudaGetSymbolAddress((void**)&u1h,   g_u1h);
  cudaGetSymbolAddress((void**)&wqkvT, g_wqkvT);
  cudaGetSymbolAddress((void**)&woT,   g_woT);
  cudaGetSymbolAddress((void**)&w12T,  g_w12T);
  cudaGetSymbolAddress((void**)&w3T,   g_w3T);

  static bool attr_set = false;
  if (!attr_set) {
    cudaFuncSetAttribute(gemm_f16_kernel,
                         cudaFuncAttributeMaxDynamicSharedMemorySize,
                         GEMM_DSMEM);
    attr_set = true;
  }

  // 0. weight transpose + fp16 convert (into merged buffers)
  transpose_f16_kernel<<<dim3(DMODEL / 32, DMODEL / 32), 256>>>(wq, wqkvT, DMODEL, DMODEL);
  transpose_f16_kernel<<<dim3(KVDIM / 32, DMODEL / 32), 256>>>(wk, wqkvT + (size_t)DMODEL * DMODEL, DMODEL, KVDIM);
  transpose_f16_kernel<<<dim3(KVDIM / 32, DMODEL / 32), 256>>>(wv, wqkvT + (size_t)(DMODEL + KVDIM) * DMODEL, DMODEL, KVDIM);
  transpose_f16_kernel<<<dim3(DMODEL / 32, DMODEL / 32), 256>>>(wo, woT, DMODEL, DMODEL);
  transpose_f16_kernel<<<dim3(HIDDIM / 32, DMODEL / 32), 256>>>(w1, w12T, DMODEL, HIDDIM);
  transpose_f16_kernel<<<dim3(HIDDIM / 32, DMODEL / 32), 256>>>(w2, w12T + (size_t)HIDDIM * DMODEL, DMODEL, HIDDIM);
  transpose_f16_kernel<<<dim3(DMODEL / 32, HIDDIM / 32), 256>>>(w3, w3T, HIDDIM, DMODEL);

  // 1. h = rmsnorm(x)  (fp16)
  rmsnorm_kernel<<<MTOK, 256>>>(x, n1, h);

  // 2. merged QKV projection  [MTOK,1280]
  gemm_f16_kernel<<<dim3(QKVDIM / 128, MTOK / 128), 256, GEMM_DSMEM>>>(
      h, wqkvT, nullptr, qkv, MTOK, QKVDIM, DMODEL);

  // 3. attention with fused QK-norm (fp16 out)
  attn_kernel<<<NB * NS * NH, 256>>>(qkv, qn, kn, o);

  // 4. x1 = x + o @ wo
  gemm_f16_kernel<<<dim3(DMODEL / 128, MTOK / 128), 256, GEMM_DSMEM>>>(
      o, woT, x, x1, MTOK, DMODEL, DMODEL);

  // 5. h2 = rmsnorm(x1) (fp16)
  rmsnorm_kernel<<<MTOK, 256>>>(x1, n2, h2);

  // 6. merged MLP up projection  [MTOK,4096]
  gemm_f16_kernel<<<dim3(HID2 / 128, MTOK / 128), 256, GEMM_DSMEM>>>(
      h2, w12T, nullptr, u12, MTOK, HID2, DMODEL);

  // 7. gate (fp16 out)
  swiglu_kernel<<<(MTOK * HIDDIM) / (256 * 4), 256>>>(u12, u1h);

  // 8. out = x1 + u1h @ w3
  gemm_f16_kernel<<<dim3(DMODEL / 128, MTOK / 128), 256, GEMM_DSMEM>>>(
      u1h, w3T, x1, out, MTOK, DMODEL, HIDDIM);
}

// round 15
// speedup vs baseline: 1.9716x; 1.2330x over previous
#include <cuda_runtime.h>
#include <cuda_fp16.h>
#include <math.h>
#include <stdint.h>

// ---------------------------------------------------------------------------
// Problem constants
// ---------------------------------------------------------------------------
#define MTOK 32768
#define DMODEL 768
#define KVDIM 256
#define QKVDIM 1280   // 768 + 256 + 256
#define HIDDIM 2048
#define HID2 4096     // w1 | w2 merged
#define NB 2
#define NT 64
#define NS 256
#define NH 12
#define NKV 4

// ---------------------------------------------------------------------------
// Scratch (device globals; no allocation allowed)
// ---------------------------------------------------------------------------
__device__ __half g_h   [MTOK * DMODEL];   // rmsnorm1(x) fp16
__device__ __half g_qkvh[MTOK * QKVDIM];   // q|k|v fp16
__device__ __half g_o   [MTOK * DMODEL];   // attn out fp16
__device__ float  g_x1  [MTOK * DMODEL];
__device__ __half g_h2  [MTOK * DMODEL];   // rmsnorm2(x1) fp16
__device__ __half g_u12 [MTOK * HID2];     // u1|u2 fp16
__device__ __half g_u1h [MTOK * HIDDIM];   // gated fp16
// transposed fp16 weights [N, K]
__device__ __half g_wqkvT[QKVDIM * DMODEL];
__device__ __half g_woT  [DMODEL * DMODEL];
__device__ __half g_w12T [HID2 * DMODEL];
__device__ __half g_w3T  [DMODEL * HIDDIM];

// ---------------------------------------------------------------------------
// helpers
// ---------------------------------------------------------------------------
__device__ __forceinline__ void mma_f16(float* c, const uint32_t* a,
                                        const uint32_t* b) {
  asm volatile(
      "mma.sync.aligned.m16n8k16.row.col.f32.f16.f16.f32 "
      "{%0,%1,%2,%3}, {%4,%5,%6,%7}, {%8,%9}, {%0,%1,%2,%3};"
      : "+f"(c[0]), "+f"(c[1]), "+f"(c[2]), "+f"(c[3])
      : "r"(a[0]), "r"(a[1]), "r"(a[2]), "r"(a[3]), "r"(b[0]), "r"(b[1]));
}

__device__ __forceinline__ void cp_async16(uint32_t smem, const void* g) {
  asm volatile("cp.async.cg.shared.global [%0], [%1], 16;" ::"r"(smem), "l"(g));
}

__device__ __forceinline__ void ldsm_x4(uint32_t* r, uint32_t addr) {
  asm volatile(
      "ldmatrix.sync.aligned.m8n8.x4.shared.b16 {%0,%1,%2,%3}, [%4];"
      : "=r"(r[0]), "=r"(r[1]), "=r"(r[2]), "=r"(r[3])
      : "r"(addr));
}

// ---------------------------------------------------------------------------
// Weight transpose + fp16 convert: out[n*K + k] = (half)in[k*N + n]
// ---------------------------------------------------------------------------
__global__ __launch_bounds__(256) void transpose_f16_kernel(
    const float* __restrict__ in, __half* __restrict__ out, int K, int N) {
  __shared__ float tile[32][33];
  int n0 = blockIdx.x * 32;
  int k0 = blockIdx.y * 32;
  int tx = threadIdx.x & 31;
  int ty = threadIdx.x >> 5;
#pragma unroll
  for (int r = ty; r < 32; r += 8)
    tile[r][tx] = in[(size_t)(k0 + r) * N + n0 + tx];
  __syncthreads();
#pragma unroll
  for (int r = ty; r < 32; r += 8)
    out[(size_t)(n0 + r) * K + k0 + tx] = __float2half(tile[tx][r]);
}

// ---------------------------------------------------------------------------
// FP16 tensor-core GEMM (ldmatrix + cp.async pipeline), templated output.
// C[M,N] = A[M,K] @ Bt[N,K]^T (+ R if non-null; R only with float out)
// ---------------------------------------------------------------------------
#define ROWH2 20
#define TILEH2 (128 * ROWH2)
#define STAGEH2 (2 * TILEH2)
#define STAGES 3
#define GEMM_DSMEM (STAGES * STAGEH2 * 4)  // 61440 bytes

template <typename OutT>
__global__ __launch_bounds__(256) void gemm_f16_kernel(
    const __half* __restrict__ A, const __half* __restrict__ Bt,
    const float* __restrict__ R, OutT* __restrict__ C,
    int M, int N, int K) {
  extern __shared__ uint32_t smh2[];

  const int tid = threadIdx.x;
  const int lane = tid & 31;
  const int warp = tid >> 5;
  const int wm = warp & 3;
  const int wn = warp >> 2;
  const int gid = lane >> 2;
  const int tin = lane & 3;
  const int grp = lane >> 3;
  const int l8 = lane & 7;
  const int bx = blockIdx.x;
  const int by = blockIdx.y;

  const __half* Ag = A + (size_t)by * 128 * K;
  const __half* Bg = Bt + (size_t)bx * 128 * K;
  const uint32_t sbase = (uint32_t)__cvta_generic_to_shared(smh2);

  const uint32_t a_lane_off =
      (uint32_t)((wm * 32 + ((grp & 1) << 3) + l8) * 80 + ((grp >> 1) << 4));
  const uint32_t b_lane_off =
      (uint32_t)((wn * 64 + ((grp >> 1) << 3) + l8) * 80 + ((grp & 1) << 4)) +
      (uint32_t)TILEH2 * 4;

  float acc[2][8][4];
#pragma unroll
  for (int mi = 0; mi < 2; mi++)
#pragma unroll
    for (int ni = 0; ni < 8; ni++)
#pragma unroll
      for (int f = 0; f < 4; f++) acc[mi][ni][f] = 0.f;

  const int ntiles = K >> 5;

  auto issue = [&](int st, int kt) {
    const uint32_t ab = sbase + (uint32_t)(st * STAGEH2) * 4;
    const uint32_t bb = ab + TILEH2 * 4;
#pragma unroll
    for (int r = 0; r < 2; r++) {
      int c = tid + r * 256;
      int row = c >> 2;
      int cc = c & 3;
      cp_async16(ab + (uint32_t)(row * ROWH2 + cc * 4) * 4,
                 Ag + (size_t)row * K + kt + cc * 8);
      cp_async16(bb + (uint32_t)(row * ROWH2 + cc * 4) * 4,
                 Bg + (size_t)row * K + kt + cc * 8);
    }
  };

  issue(0, 0);
  asm volatile("cp.async.commit_group;");
  if (ntiles > 1) issue(1, 32);
  asm volatile("cp.async.commit_group;");

  for (int it = 0; it < ntiles; ++it) {
    asm volatile("cp.async.wait_group 1;");
    __syncthreads();
    if (it + 2 < ntiles) issue((it + 2) % 3, (it + 2) * 32);
    asm volatile("cp.async.commit_group;");

    const uint32_t stage_byte = sbase + (uint32_t)((it % 3) * STAGEH2) * 4;

#pragma unroll
    for (int ks = 0; ks < 2; ks++) {
      const uint32_t kb = ks * 32;
      uint32_t af[2][4];
#pragma unroll
      for (int mi = 0; mi < 2; mi++)
        ldsm_x4(af[mi], stage_byte + a_lane_off + (uint32_t)(mi * 16 * 80) + kb);
      uint32_t bf[8][2];
#pragma unroll
      for (int p = 0; p < 4; p++) {
        uint32_t t[4];
        ldsm_x4(t, stage_byte + b_lane_off + (uint32_t)(p * 16 * 80) + kb);
        bf[2 * p][0] = t[0];
        bf[2 * p][1] = t[1];
        bf[2 * p + 1][0] = t[2];
        bf[2 * p + 1][1] = t[3];
      }
#pragma unroll
      for (int mi = 0; mi < 2; mi++)
#pragma unroll
        for (int ni = 0; ni < 8; ni++) mma_f16(acc[mi][ni], af[mi], bf[ni]);
    }
  }

  // epilogue
#pragma unroll
  for (int mi = 0; mi < 2; mi++) {
#pragma unroll
    for (int ni = 0; ni < 8; ni++) {
      int row = by * 128 + wm * 32 + mi * 16 + gid;
      int col = bx * 128 + wn * 64 + ni * 8 + (tin << 1);
      size_t o0 = (size_t)row * N + col;
      size_t o1 = (size_t)(row + 8) * N + col;
      float2 v0 = {acc[mi][ni][0], acc[mi][ni][1]};
      float2 v1 = {acc[mi][ni][2], acc[mi][ni][3]};
      if (R) {
        float2 r0 = *(const float2*)(R + o0);
        float2 r1 = *(const float2*)(R + o1);
        v0.x += r0.x; v0.y += r0.y;
        v1.x += r1.x; v1.y += r1.y;
      }
      if (sizeof(OutT) == 2) {
        __half2* c0 = (__half2*)((__half*)C + o0);
        __half2* c1 = (__half2*)((__half*)C + o1);
        *c0 = __floats2half2_rn(v0.x, v0.y);
        *c1 = __floats2half2_rn(v1.x, v1.y);
      } else {
        *(float2*)((float*)C + o0) = v0;
        *(float2*)((float*)C + o1) = v1;
      }
    }
  }
}

// ---------------------------------------------------------------------------
// Row RMSNorm over 768 -> fp16 output
// ---------------------------------------------------------------------------
__global__ __launch_bounds__(256) void rmsnorm_kernel(
    const float* __restrict__ x, const float* __restrict__ w,
    __half* __restrict__ out) {
  const int row = blockIdx.x;
  const float* xr = x + (size_t)row * DMODEL;
  __half* orow = out + (size_t)row * DMODEL;
  const int tid = threadIdx.x;
  float v0 = xr[tid];
  float v1 = xr[tid + 256];
  float v2 = xr[tid + 512];
  float s = v0 * v0 + v1 * v1 + v2 * v2;
#pragma unroll
  for (int off = 16; off > 0; off >>= 1)
    s += __shfl_xor_sync(0xffffffffu, s, off);
  __shared__ float ws[8];
  if ((tid & 31) == 0) ws[tid >> 5] = s;
  __syncthreads();
  float tot = ws[0] + ws[1] + ws[2] + ws[3] + ws[4] + ws[5] + ws[6] + ws[7];
  float rs = rsqrtf(tot * (1.0f / (float)DMODEL) + 1e-6f);
  orow[tid]       = __float2half(v0 * rs * w[tid]);
  orow[tid + 256] = __float2half(v1 * rs * w[tid + 256]);
  orow[tid + 512] = __float2half(v2 * rs * w[tid + 512]);
}

// ---------------------------------------------------------------------------
// Attention with fused QK-norm, float4-vectorized smem access.
// One block per (b, s, h); qkv fp16 [tok][1280]; fp16 output.
// Smem stride 72 floats: conflict-free float4 LDS in QK (j=jj*4+tj) and PV.
// ---------------------------------------------------------------------------
#define AST 72
__global__ __launch_bounds__(256) void attn_kernel(
    const __half* __restrict__ qkv, const float* __restrict__ qn,
    const float* __restrict__ kn, __half* __restrict__ o) {
  __shared__ float Qs[64][AST];
  __shared__ float Ks[64][AST];
  const int idx = blockIdx.x;
  const int h = idx % NH;
  const int s = (idx / NH) % NS;
  const int b = idx / (NH * NS);
  const int kvh = h / (NH / NKV);
  const int tid = threadIdx.x;

  for (int i = tid; i < 64 * 64; i += 256) {
    int t = i >> 6, d = i & 63;
    size_t tok = (size_t)((b * NT + t) * NS + s);
    Qs[t][d] = __half2float(qkv[tok * QKVDIM + h * 64 + d]);
    Ks[t][d] = __half2float(qkv[tok * QKVDIM + DMODEL + kvh * 64 + d]);
  }
  __syncthreads();

  const int row = tid >> 2;
  const int tj  = tid & 3;

  // fused QK RMSNorm (per row of 64; each tj handles 16 columns)
  {
    float sq = 0.f, sk = 0.f;
#pragma unroll
    for (int jj = 0; jj < 16; jj++) {
      float a = Qs[row][tj * 16 + jj];
      float c = Ks[row][tj * 16 + jj];
      sq += a * a;
      sk += c * c;
    }
    sq += __shfl_xor_sync(0xffffffffu, sq, 1);
    sq += __shfl_xor_sync(0xffffffffu, sq, 2);
    sk += __shfl_xor_sync(0xffffffffu, sk, 1);
    sk += __shfl_xor_sync(0xffffffffu, sk, 2);
    float rq = rsqrtf(sq * (1.0f / 64.0f) + 1e-6f);
    float rk = rsqrtf(sk * (1.0f / 64.0f) + 1e-6f);
#pragma unroll
    for (int jj = 0; jj < 16; jj++) {
      int d = tj * 16 + jj;
      Qs[row][d] *= rq * qn[d];
      Ks[row][d] *= rk * kn[d];
    }
  }
  __syncthreads();

  // logits: thread (row, tj) computes j = jj*4 + tj  (float4 over d)
  float lg[16];
#pragma unroll
  for (int jj = 0; jj < 16; jj++) lg[jj] = 0.f;
#pragma unroll 4
  for (int d4 = 0; d4 < 16; d4++) {
    float4 qv = *(const float4*)&Qs[row][d4 * 4];
#pragma unroll
    for (int jj = 0; jj < 16; jj++) {
      int j = jj * 4 + tj;
      float4 kv = *(const float4*)&Ks[j][d4 * 4];
      lg[jj] += qv.x * kv.x + qv.y * kv.y + qv.z * kv.z + qv.w * kv.w;
    }
  }
#pragma unroll
  for (int jj = 0; jj < 16; jj++) {
    int j = jj * 4 + tj;
    float acc = lg[jj] * 0.125f;
    acc = 50.0f * tanhf(acc * 0.02f);
    lg[jj] = (j <= row) ? acc : -INFINITY;
  }

  float mx = lg[0];
#pragma unroll
  for (int jj = 1; jj < 16; jj++) mx = fmaxf(mx, lg[jj]);
  mx = fmaxf(mx, __shfl_xor_sync(0xffffffffu, mx, 1));
  mx = fmaxf(mx, __shfl_xor_sync(0xffffffffu, mx, 2));
  float sum = 0.f;
#pragma unroll
  for (int jj = 0; jj < 16; jj++) {
    float e = __expf(lg[jj] - mx);
    lg[jj] = e;
    sum += e;
  }
  sum += __shfl_xor_sync(0xffffffffu, sum, 1);
  sum += __shfl_xor_sync(0xffffffffu, sum, 2);
  float inv = 1.0f / sum;

  __syncthreads();
#pragma unroll
  for (int jj = 0; jj < 16; jj++) Qs[row][jj * 4 + tj] = lg[jj] * inv;
  for (int i = tid; i < 64 * 64; i += 256) {
    int t = i >> 6, d = i & 63;
    size_t tok = (size_t)((b * NT + t) * NS + s);
    Ks[t][d] = __half2float(qkv[tok * QKVDIM + DMODEL + KVDIM + kvh * 64 + d]);
  }
  __syncthreads();

  // PV: thread (row, tj) computes dd = dd4*16 + tj*4 + i  (float4 over dd)
  float4 acc4[4];
#pragma unroll
  for (int d4 = 0; d4 < 4; d4++) acc4[d4] = make_float4(0.f, 0.f, 0.f, 0.f);
  for (int j = 0; j < 64; j++) {
    float p = Qs[row][j];
#pragma unroll
    for (int d4 = 0; d4 < 4; d4++) {
      float4 kv = *(const float4*)&Ks[j][d4 * 16 + tj * 4];
      acc4[d4].x += p * kv.x;
      acc4[d4].y += p * kv.y;
      acc4[d4].z += p * kv.z;
      acc4[d4].w += p * kv.w;
    }
  }
  size_t tok = (size_t)((b * NT + row) * NS + s);
  __half* obase = o + tok * DMODEL + h * 64;
#pragma unroll
  for (int d4 = 0; d4 < 4; d4++) {
    __half2* dst = (__half2*)(obase + d4 * 16 + tj * 4);
    dst[0] = __floats2half2_rn(acc4[d4].x, acc4[d4].y);
    dst[1] = __floats2half2_rn(acc4[d4].z, acc4[d4].w);
  }
}

// ---------------------------------------------------------------------------
// SwiGLU gate on fp16 merged buffer
// ---------------------------------------------------------------------------
__global__ __launch_bounds__(256) void swiglu_kernel(
    const __half* __restrict__ u12, __half* __restrict__ u1h) {
  size_t idx = (size_t)blockIdx.x * 256 + threadIdx.x;
  size_t c4 = idx * 4;
  size_t r = c4 >> 11;
  size_t c = c4 & 2047;
  const __half2* pa = (const __half2*)(u12 + r * HID2 + c);
  const __half2* pb = (const __half2*)(u12 + r * HID2 + HIDDIM + c);
  float2 a01 = __half22float2(pa[0]);
  float2 a23 = __half22float2(pa[1]);
  float2 b01 = __half22float2(pb[0]);
  float2 b23 = __half22float2(pb[1]);
  float r0 = a01.x / (1.f + __expf(-a01.x)) * b01.x;
  float r1 = a01.y / (1.f + __expf(-a01.y)) * b01.y;
  float r2 = a23.x / (1.f + __expf(-a23.x)) * b23.x;
  float r3 = a23.y / (1.f + __expf(-a23.y)) * b23.y;
  __half2* dst = (__half2*)(u1h + r * HIDDIM + c);
  dst[0] = __floats2half2_rn(r0, r1);
  dst[1] = __floats2half2_rn(r2, r3);
}

// ---------------------------------------------------------------------------
// Launch
// ---------------------------------------------------------------------------
extern "C" void kernel_launch(void* const* d_in, const int* in_sizes, int n_in,
                              void* d_out, int out_size) {
  const float* x  = (const float*)d_in[0];
  const float* n1 = (const float*)d_in[1];
  const float* n2 = (const float*)d_in[2];
  const float* qn = (const float*)d_in[3];
  const float* kn = (const float*)d_in[4];
  const float* wq = (const float*)d_in[5];
  const float* wk = (const float*)d_in[6];
  const float* wv = (const float*)d_in[7];
  const float* wo = (const float*)d_in[8];
  const float* w1 = (const float*)d_in[9];
  const float* w2 = (const float*)d_in[10];
  const float* w3 = (const float*)d_in[11];
  float* out = (float*)d_out;

  __half *h, *qkvh, *o, *h2, *u12, *u1h;
  float *x1;
  __half *wqkvT, *woT, *w12T, *w3T;
  cudaGetSymbolAddress((void**)&h,     g_h);
  cudaGetSymbolAddress((void**)&qkvh,  g_qkvh);
  cudaGetSymbolAddress((void**)&o,     g_o);
  cudaGetSymbolAddress((void**)&x1,    g_x1);
  cudaGetSymbolAddress((void**)&h2,    g_h2);
  cudaGetSymbolAddress((void**)&u12,   g_u12);
  cudaGetSymbolAddress((void**)&u1h,   g_u1h);
  cudaGetSymbolAddress((void**)&wqkvT, g_wqkvT);
  cudaGetSymbolAddress((void**)&woT,   g_woT);
  cudaGetSymbolAddress((void**)&w12T,  g_w12T);
  cudaGetSymbolAddress((void**)&w3T,   g_w3T);

  static bool attr_set = false;
  if (!attr_set) {
    cudaFuncSetAttribute(gemm_f16_kernel<float>,
                         cudaFuncAttributeMaxDynamicSharedMemorySize,
                         GEMM_DSMEM);
    cudaFuncSetAttribute(gemm_f16_kernel<__half>,
                         cudaFuncAttributeMaxDynamicSharedMemorySize,
                         GEMM_DSMEM);
    attr_set = true;
  }

  // 0. weight transpose + fp16 convert (into merged buffers)
  transpose_f16_kernel<<<dim3(DMODEL / 32, DMODEL / 32), 256>>>(wq, wqkvT, DMODEL, DMODEL);
  transpose_f16_kernel<<<dim3(KVDIM / 32, DMODEL / 32), 256>>>(wk, wqkvT + (size_t)DMODEL * DMODEL, DMODEL, KVDIM);
  transpose_f16_kernel<<<dim3(KVDIM / 32, DMODEL / 32), 256>>>(wv, wqkvT + (size_t)(DMODEL + KVDIM) * DMODEL, DMODEL, KVDIM);
  transpose_f16_kernel<<<dim3(DMODEL / 32, DMODEL / 32), 256>>>(wo, woT, DMODEL, DMODEL);
  transpose_f16_kernel<<<dim3(HIDDIM / 32, DMODEL / 32), 256>>>(w1, w12T, DMODEL, HIDDIM);
  transpose_f16_kernel<<<dim3(HIDDIM / 32, DMODEL / 32), 256>>>(w2, w12T + (size_t)HIDDIM * DMODEL, DMODEL, HIDDIM);
  transpose_f16_kernel<<<dim3(DMODEL / 32, HIDDIM / 32), 256>>>(w3, w3T, HIDDIM, DMODEL);

  // 1. h = rmsnorm(x)  (fp16)
  rmsnorm_kernel<<<MTOK, 256>>>(x, n1, h);

  // 2. merged QKV projection  [MTOK,1280] fp16
  gemm_f16_kernel<__half><<<dim3(QKVDIM / 128, MTOK / 128), 256, GEMM_DSMEM>>>(
      h, wqkvT, nullptr, qkvh, MTOK, QKVDIM, DMODEL);

  // 3. attention with fused QK-norm (fp16 out)
  attn_kernel<<<NB * NS * NH, 256>>>(qkvh, qn, kn, o);

  // 4. x1 = x + o @ wo  (fp32 out)
  gemm_f16_kernel<float><<<dim3(DMODEL / 128, MTOK / 128), 256, GEMM_DSMEM>>>(
      o, woT, x, x1, MTOK, DMODEL, DMODEL);

  // 5. h2 = rmsnorm(x1) (fp16)
  rmsnorm_kernel<<<MTOK, 256>>>(x1, n2, h2);

  // 6. merged MLP up projection  [MTOK,4096] fp16
  gemm_f16_kernel<__half><<<dim3(HID2 / 128, MTOK / 128), 256, GEMM_DSMEM>>>(
      h2, w12T, nullptr, u12, MTOK, HID2, DMODEL);

  // 7. gate (fp16 out)
  swiglu_kernel<<<(MTOK * HIDDIM) / (256 * 4), 256>>>(u12, u1h);

  // 8. out = x1 + u1h @ w3  (fp32 out)
  gemm_f16_kernel<float><<<dim3(DMODEL / 128, MTOK / 128), 256, GEMM_DSMEM>>>(
      u1h, w3T, x1, out, MTOK, DMODEL, HIDDIM);
}

// round 16
// speedup vs baseline: 2.0686x; 1.0492x over previous
#include <cuda_runtime.h>
#include <cuda_fp16.h>
#include <math.h>
#include <stdint.h>

// ---------------------------------------------------------------------------
// Problem constants
// ---------------------------------------------------------------------------
#define MTOK 32768
#define DMODEL 768
#define KVDIM 256
#define QKVDIM 1280   // 768 + 256 + 256
#define HIDDIM 2048
#define HID2 4096     // w1 | w2 merged
#define NB 2
#define NT 64
#define NS 256
#define NH 12
#define NKV 4

// ---------------------------------------------------------------------------
// Scratch (device globals; no allocation allowed)
// ---------------------------------------------------------------------------
__device__ __half g_h   [MTOK * DMODEL];   // rmsnorm1(x) fp16
__device__ __half g_qkvh[MTOK * QKVDIM];   // q|k|v fp16
__device__ __half g_o   [MTOK * DMODEL];   // attn out fp16
__device__ float  g_x1  [MTOK * DMODEL];
__device__ __half g_h2  [MTOK * DMODEL];   // rmsnorm2(x1) fp16
__device__ __half g_u12 [MTOK * HID2];     // u1|u2 fp16
__device__ __half g_u1h [MTOK * HIDDIM];   // gated fp16
// transposed fp16 weights [N, K]
__device__ __half g_wqkvT[QKVDIM * DMODEL];
__device__ __half g_woT  [DMODEL * DMODEL];
__device__ __half g_w12T [HID2 * DMODEL];
__device__ __half g_w3T  [DMODEL * HIDDIM];

// ---------------------------------------------------------------------------
// helpers
// ---------------------------------------------------------------------------
__device__ __forceinline__ void mma_f16(float* c, const uint32_t* a,
                                        const uint32_t* b) {
  asm volatile(
      "mma.sync.aligned.m16n8k16.row.col.f32.f16.f16.f32 "
      "{%0,%1,%2,%3}, {%4,%5,%6,%7}, {%8,%9}, {%0,%1,%2,%3};"
      : "+f"(c[0]), "+f"(c[1]), "+f"(c[2]), "+f"(c[3])
      : "r"(a[0]), "r"(a[1]), "r"(a[2]), "r"(a[3]), "r"(b[0]), "r"(b[1]));
}

__device__ __forceinline__ void cp_async16(uint32_t smem, const void* g) {
  asm volatile("cp.async.cg.shared.global [%0], [%1], 16;" ::"r"(smem), "l"(g));
}

__device__ __forceinline__ void ldsm_x4(uint32_t* r, uint32_t addr) {
  asm volatile(
      "ldmatrix.sync.aligned.m8n8.x4.shared.b16 {%0,%1,%2,%3}, [%4];"
      : "=r"(r[0]), "=r"(r[1]), "=r"(r[2]), "=r"(r[3])
      : "r"(addr));
}

// ---------------------------------------------------------------------------
// Tile transpose helper + two merged transpose kernels (fewer launches; also
// positions the wo-GEMM as the 6th launch so ncu -s 5 -c 1 captures a GEMM)
// ---------------------------------------------------------------------------
__device__ __forceinline__ void transpose_tile(const float* __restrict__ in,
                                               __half* __restrict__ out,
                                               int K, int N, int bx, int by) {
  __shared__ float tile[32][33];
  int n0 = bx * 32;
  int k0 = by * 32;
  int tx = threadIdx.x & 31;
  int ty = threadIdx.x >> 5;
#pragma unroll
  for (int r = ty; r < 32; r += 8)
    tile[r][tx] = in[(size_t)(k0 + r) * N + n0 + tx];
  __syncthreads();
#pragma unroll
  for (int r = ty; r < 32; r += 8)
    out[(size_t)(n0 + r) * K + k0 + tx] = __float2half(tile[tx][r]);
}

// grid 1536: wq(576) | wk(192) | wv(192) | wo(576)
__global__ __launch_bounds__(256) void transpose_qkvwo_kernel(
    const float* __restrict__ wq, const float* __restrict__ wk,
    const float* __restrict__ wv, const float* __restrict__ wo,
    __half* __restrict__ wqkvT, __half* __restrict__ woT) {
  int bid = blockIdx.x;
  if (bid < 576) {
    transpose_tile(wq, wqkvT, DMODEL, DMODEL, bid % 24, bid / 24);
  } else if (bid < 768) {
    int b = bid - 576;
    transpose_tile(wk, wqkvT + (size_t)DMODEL * DMODEL, DMODEL, KVDIM,
                   b % 8, b / 8);
  } else if (bid < 960) {
    int b = bid - 768;
    transpose_tile(wv, wqkvT + (size_t)(DMODEL + KVDIM) * DMODEL, DMODEL,
                   KVDIM, b % 8, b / 8);
  } else {
    int b = bid - 960;
    transpose_tile(wo, woT, DMODEL, DMODEL, b % 24, b / 24);
  }
}

// grid 4608: w1(1536) | w2(1536) | w3(1536)
__global__ __launch_bounds__(256) void transpose_mlp_kernel(
    const float* __restrict__ w1, const float* __restrict__ w2,
    const float* __restrict__ w3, __half* __restrict__ w12T,
    __half* __restrict__ w3T) {
  int bid = blockIdx.x;
  if (bid < 1536) {
    transpose_tile(w1, w12T, DMODEL, HIDDIM, bid % 64, bid / 64);
  } else if (bid < 3072) {
    int b = bid - 1536;
    transpose_tile(w2, w12T + (size_t)HIDDIM * DMODEL, DMODEL, HIDDIM,
                   b % 64, b / 64);
  } else {
    int b = bid - 3072;
    transpose_tile(w3, w3T, HIDDIM, DMODEL, b % 24, b / 24);
  }
}

// ---------------------------------------------------------------------------
// FP16 tensor-core GEMM (ldmatrix + 5-stage cp.async pipeline), templated out.
// C[M,N] = A[M,K] @ Bt[N,K]^T (+ R if non-null; R only with float out)
// 128x128 tile, BK=32, 256 threads, warp tile 32x64, mma m16n8k16.
// 5 stages (102,400 B dsmem) -> 4-tile load lookahead hides L2/DRAM latency.
// ---------------------------------------------------------------------------
#define ROWH2 20
#define TILEH2 (128 * ROWH2)
#define STAGEH2 (2 * TILEH2)
#define STAGES 5
#define GEMM_DSMEM (STAGES * STAGEH2 * 4)  // 102400 bytes

template <typename OutT>
__global__ __launch_bounds__(256) void gemm_f16_kernel(
    const __half* __restrict__ A, const __half* __restrict__ Bt,
    const float* __restrict__ R, OutT* __restrict__ C,
    int M, int N, int K) {
  extern __shared__ uint32_t smh2[];

  const int tid = threadIdx.x;
  const int lane = tid & 31;
  const int warp = tid >> 5;
  const int wm = warp & 3;
  const int wn = warp >> 2;
  const int gid = lane >> 2;
  const int tin = lane & 3;
  const int grp = lane >> 3;
  const int l8 = lane & 7;
  const int bx = blockIdx.x;
  const int by = blockIdx.y;

  const __half* Ag = A + (size_t)by * 128 * K;
  const __half* Bg = Bt + (size_t)bx * 128 * K;
  const uint32_t sbase = (uint32_t)__cvta_generic_to_shared(smh2);

  const uint32_t a_lane_off =
      (uint32_t)((wm * 32 + ((grp & 1) << 3) + l8) * 80 + ((grp >> 1) << 4));
  const uint32_t b_lane_off =
      (uint32_t)((wn * 64 + ((grp >> 1) << 3) + l8) * 80 + ((grp & 1) << 4)) +
      (uint32_t)TILEH2 * 4;

  float acc[2][8][4];
#pragma unroll
  for (int mi = 0; mi < 2; mi++)
#pragma unroll
    for (int ni = 0; ni < 8; ni++)
#pragma unroll
      for (int f = 0; f < 4; f++) acc[mi][ni][f] = 0.f;

  const int ntiles = K >> 5;

  auto issue = [&](int st, int kt) {
    const uint32_t ab = sbase + (uint32_t)(st * STAGEH2) * 4;
    const uint32_t bb = ab + TILEH2 * 4;
#pragma unroll
    for (int r = 0; r < 2; r++) {
      int c = tid + r * 256;
      int row = c >> 2;
      int cc = c & 3;
      cp_async16(ab + (uint32_t)(row * ROWH2 + cc * 4) * 4,
                 Ag + (size_t)row * K + kt + cc * 8);
      cp_async16(bb + (uint32_t)(row * ROWH2 + cc * 4) * 4,
                 Bg + (size_t)row * K + kt + cc * 8);
    }
  };

  // prologue: 4 tiles in flight
#pragma unroll
  for (int p = 0; p < STAGES - 1; p++) {
    if (p < ntiles) issue(p, p * 32);
    asm volatile("cp.async.commit_group;");
  }

  for (int it = 0; it < ntiles; ++it) {
    asm volatile("cp.async.wait_group %0;" ::"n"(STAGES - 2));
    __syncthreads();
    if (it + STAGES - 1 < ntiles)
      issue((it + STAGES - 1) % STAGES, (it + STAGES - 1) * 32);
    asm volatile("cp.async.commit_group;");

    const uint32_t stage_byte = sbase + (uint32_t)((it % STAGES) * STAGEH2) * 4;

#pragma unroll
    for (int ks = 0; ks < 2; ks++) {
      const uint32_t kb = ks * 32;
      uint32_t af[2][4];
#pragma unroll
      for (int mi = 0; mi < 2; mi++)
        ldsm_x4(af[mi], stage_byte + a_lane_off + (uint32_t)(mi * 16 * 80) + kb);
      uint32_t bf[8][2];
#pragma unroll
      for (int p = 0; p < 4; p++) {
        uint32_t t[4];
        ldsm_x4(t, stage_byte + b_lane_off + (uint32_t)(p * 16 * 80) + kb);
        bf[2 * p][0] = t[0];
        bf[2 * p][1] = t[1];
        bf[2 * p + 1][0] = t[2];
        bf[2 * p + 1][1] = t[3];
      }
#pragma unroll
      for (int mi = 0; mi < 2; mi++)
#pragma unroll
        for (int ni = 0; ni < 8; ni++) mma_f16(acc[mi][ni], af[mi], bf[ni]);
    }
  }

  // epilogue
#pragma unroll
  for (int mi = 0; mi < 2; mi++) {
#pragma unroll
    for (int ni = 0; ni < 8; ni++) {
      int row = by * 128 + wm * 32 + mi * 16 + gid;
      int col = bx * 128 + wn * 64 + ni * 8 + (tin << 1);
      size_t o0 = (size_t)row * N + col;
      size_t o1 = (size_t)(row + 8) * N + col;
      float2 v0 = {acc[mi][ni][0], acc[mi][ni][1]};
      float2 v1 = {acc[mi][ni][2], acc[mi][ni][3]};
      if (R) {
        float2 r0 = *(const float2*)(R + o0);
        float2 r1 = *(const float2*)(R + o1);
        v0.x += r0.x; v0.y += r0.y;
        v1.x += r1.x; v1.y += r1.y;
      }
      if (sizeof(OutT) == 2) {
        __half2* c0 = (__half2*)((__half*)C + o0);
        __half2* c1 = (__half2*)((__half*)C + o1);
        *c0 = __floats2half2_rn(v0.x, v0.y);
        *c1 = __floats2half2_rn(v1.x, v1.y);
      } else {
        *(float2*)((float*)C + o0) = v0;
        *(float2*)((float*)C + o1) = v1;
      }
    }
  }
}

// ---------------------------------------------------------------------------
// Row RMSNorm over 768 -> fp16 output
// ---------------------------------------------------------------------------
__global__ __launch_bounds__(256) void rmsnorm_kernel(
    const float* __restrict__ x, const float* __restrict__ w,
    __half* __restrict__ out) {
  const int row = blockIdx.x;
  const float* xr = x + (size_t)row * DMODEL;
  __half* orow = out + (size_t)row * DMODEL;
  const int tid = threadIdx.x;
  float v0 = xr[tid];
  float v1 = xr[tid + 256];
  float v2 = xr[tid + 512];
  float s = v0 * v0 + v1 * v1 + v2 * v2;
#pragma unroll
  for (int off = 16; off > 0; off >>= 1)
    s += __shfl_xor_sync(0xffffffffu, s, off);
  __shared__ float ws[8];
  if ((tid & 31) == 0) ws[tid >> 5] = s;
  __syncthreads();
  float tot = ws[0] + ws[1] + ws[2] + ws[3] + ws[4] + ws[5] + ws[6] + ws[7];
  float rs = rsqrtf(tot * (1.0f / (float)DMODEL) + 1e-6f);
  orow[tid]       = __float2half(v0 * rs * w[tid]);
  orow[tid + 256] = __float2half(v1 * rs * w[tid + 256]);
  orow[tid + 512] = __float2half(v2 * rs * w[tid + 512]);
}

// ---------------------------------------------------------------------------
// Attention with fused QK-norm, float4-vectorized smem access.
// ---------------------------------------------------------------------------
#define AST 72
__global__ __launch_bounds__(256) void attn_kernel(
    const __half* __restrict__ qkv, const float* __restrict__ qn,
    const float* __restrict__ kn, __half* __restrict__ o) {
  __shared__ float Qs[64][AST];
  __shared__ float Ks[64][AST];
  const int idx = blockIdx.x;
  const int h = idx % NH;
  const int s = (idx / NH) % NS;
  const int b = idx / (NH * NS);
  const int kvh = h / (NH / NKV);
  const int tid = threadIdx.x;

  for (int i = tid; i < 64 * 64; i += 256) {
    int t = i >> 6, d = i & 63;
    size_t tok = (size_t)((b * NT + t) * NS + s);
    Qs[t][d] = __half2float(qkv[tok * QKVDIM + h * 64 + d]);
    Ks[t][d] = __half2float(qkv[tok * QKVDIM + DMODEL + kvh * 64 + d]);
  }
  __syncthreads();

  const int row = tid >> 2;
  const int tj  = tid & 3;

  {
    float sq = 0.f, sk = 0.f;
#pragma unroll
    for (int jj = 0; jj < 16; jj++) {
      float a = Qs[row][tj * 16 + jj];
      float c = Ks[row][tj * 16 + jj];
      sq += a * a;
      sk += c * c;
    }
    sq += __shfl_xor_sync(0xffffffffu, sq, 1);
    sq += __shfl_xor_sync(0xffffffffu, sq, 2);
    sk += __shfl_xor_sync(0xffffffffu, sk, 1);
    sk += __shfl_xor_sync(0xffffffffu, sk, 2);
    float rq = rsqrtf(sq * (1.0f / 64.0f) + 1e-6f);
    float rk = rsqrtf(sk * (1.0f / 64.0f) + 1e-6f);
#pragma unroll
    for (int jj = 0; jj < 16; jj++) {
      int d = tj * 16 + jj;
      Qs[row][d] *= rq * qn[d];
      Ks[row][d] *= rk * kn[d];
    }
  }
  __syncthreads();

  float lg[16];
#pragma unroll
  for (int jj = 0; jj < 16; jj++) lg[jj] = 0.f;
#pragma unroll 4
  for (int d4 = 0; d4 < 16; d4++) {
    float4 qv = *(const float4*)&Qs[row][d4 * 4];
#pragma unroll
    for (int jj = 0; jj < 16; jj++) {
      int j = jj * 4 + tj;
      float4 kv = *(const float4*)&Ks[j][d4 * 4];
      lg[jj] += qv.x * kv.x + qv.y * kv.y + qv.z * kv.z + qv.w * kv.w;
    }
  }
#pragma unroll
  for (int jj = 0; jj < 16; jj++) {
    int j = jj * 4 + tj;
    float acc = lg[jj] * 0.125f;
    acc = 50.0f * tanhf(acc * 0.02f);
    lg[jj] = (j <= row) ? acc : -INFINITY;
  }

  float mx = lg[0];
#pragma unroll
  for (int jj = 1; jj < 16; jj++) mx = fmaxf(mx, lg[jj]);
  mx = fmaxf(mx, __shfl_xor_sync(0xffffffffu, mx, 1));
  mx = fmaxf(mx, __shfl_xor_sync(0xffffffffu, mx, 2));
  float sum = 0.f;
#pragma unroll
  for (int jj = 0; jj < 16; jj++) {
    float e = __expf(lg[jj] - mx);
    lg[jj] = e;
    sum += e;
  }
  sum += __shfl_xor_sync(0xffffffffu, sum, 1);
  sum += __shfl_xor_sync(0xffffffffu, sum, 2);
  float inv = 1.0f / sum;

  __syncthreads();
#pragma unroll
  for (int jj = 0; jj < 16; jj++) Qs[row][jj * 4 + tj] = lg[jj] * inv;
  for (int i = tid; i < 64 * 64; i += 256) {
    int t = i >> 6, d = i & 63;
    size_t tok = (size_t)((b * NT + t) * NS + s);
    Ks[t][d] = __half2float(qkv[tok * QKVDIM + DMODEL + KVDIM + kvh * 64 + d]);
  }
  __syncthreads();

  float4 acc4[4];
#pragma unroll
  for (int d4 = 0; d4 < 4; d4++) acc4[d4] = make_float4(0.f, 0.f, 0.f, 0.f);
  for (int j = 0; j < 64; j++) {
    float p = Qs[row][j];
#pragma unroll
    for (int d4 = 0; d4 < 4; d4++) {
      float4 kv = *(const float4*)&Ks[j][d4 * 16 + tj * 4];
      acc4[d4].x += p * kv.x;
      acc4[d4].y += p * kv.y;
      acc4[d4].z += p * kv.z;
      acc4[d4].w += p * kv.w;
    }
  }
  size_t tok = (size_t)((b * NT + row) * NS + s);
  __half* obase = o + tok * DMODEL + h * 64;
#pragma unroll
  for (int d4 = 0; d4 < 4; d4++) {
    __half2* dst = (__half2*)(obase + d4 * 16 + tj * 4);
    dst[0] = __floats2half2_rn(acc4[d4].x, acc4[d4].y);
    dst[1] = __floats2half2_rn(acc4[d4].z, acc4[d4].w);
  }
}

// ---------------------------------------------------------------------------
// SwiGLU gate on fp16 merged buffer
// ---------------------------------------------------------------------------
__global__ __launch_bounds__(256) void swiglu_kernel(
    const __half* __restrict__ u12, __half* __restrict__ u1h) {
  size_t idx = (size_t)blockIdx.x * 256 + threadIdx.x;
  size_t c4 = idx * 4;
  size_t r = c4 >> 11;
  size_t c = c4 & 2047;
  const __half2* pa = (const __half2*)(u12 + r * HID2 + c);
  const __half2* pb = (const __half2*)(u12 + r * HID2 + HIDDIM + c);
  float2 a01 = __half22float2(pa[0]);
  float2 a23 = __half22float2(pa[1]);
  float2 b01 = __half22float2(pb[0]);
  float2 b23 = __half22float2(pb[1]);
  float r0 = a01.x / (1.f + __expf(-a01.x)) * b01.x;
  float r1 = a01.y / (1.f + __expf(-a01.y)) * b01.y;
  float r2 = a23.x / (1.f + __expf(-a23.x)) * b23.x;
  float r3 = a23.y / (1.f + __expf(-a23.y)) * b23.y;
  __half2* dst = (__half2*)(u1h + r * HIDDIM + c);
  dst[0] = __floats2half2_rn(r0, r1);
  dst[1] = __floats2half2_rn(r2, r3);
}

// ---------------------------------------------------------------------------
// Launch
// ---------------------------------------------------------------------------
extern "C" void kernel_launch(void* const* d_in, const int* in_sizes, int n_in,
                              void* d_out, int out_size) {
  const float* x  = (const float*)d_in[0];
  const float* n1 = (const float*)d_in[1];
  const float* n2 = (const float*)d_in[2];
  const float* qn = (const float*)d_in[3];
  const float* kn = (const float*)d_in[4];
  const float* wq = (const float*)d_in[5];
  const float* wk = (const float*)d_in[6];
  const float* wv = (const float*)d_in[7];
  const float* wo = (const float*)d_in[8];
  const float* w1 = (const float*)d_in[9];
  const float* w2 = (const float*)d_in[10];
  const float* w3 = (const float*)d_in[11];
  float* out = (float*)d_out;

  __half *h, *qkvh, *o, *h2, *u12, *u1h;
  float *x1;
  __half *wqkvT, *woT, *w12T, *w3T;
  cudaGetSymbolAddress((void**)&h,     g_h);
  cudaGetSymbolAddress((void**)&qkvh,  g_qkvh);
  cudaGetSymbolAddress((void**)&o,     g_o);
  cudaGetSymbolAddress((void**)&x1,    g_x1);
  cudaGetSymbolAddress((void**)&h2,    g_h2);
  cudaGetSymbolAddress((void**)&u12,   g_u12);
  cudaGetSymbolAddress((void**)&u1h,   g_u1h);
  cudaGetSymbolAddress((void**)&wqkvT, g_wqkvT);
  cudaGetSymbolAddress((void**)&woT,   g_woT);
  cudaGetSymbolAddress((void**)&w12T,  g_w12T);
  cudaGetSymbolAddress((void**)&w3T,   g_w3T);

  static bool attr_set = false;
  if (!attr_set) {
    cudaFuncSetAttribute(gemm_f16_kernel<float>,
                         cudaFuncAttributeMaxDynamicSharedMemorySize,
                         GEMM_DSMEM);
    cudaFuncSetAttribute(gemm_f16_kernel<__half>,
                         cudaFuncAttributeMaxDynamicSharedMemorySize,
                         GEMM_DSMEM);
    attr_set = true;
  }

  // launches 1-2: merged weight transposes
  transpose_qkvwo_kernel<<<1536, 256>>>(wq, wk, wv, wo, wqkvT, woT);
  transpose_mlp_kernel<<<4608, 256>>>(w1, w2, w3, w12T, w3T);

  // launch 3: h = rmsnorm(x)  (fp16)
  rmsnorm_kernel<<<MTOK, 256>>>(x, n1, h);

  // launch 4: merged QKV projection  [MTOK,1280] fp16
  gemm_f16_kernel<__half><<<dim3(QKVDIM / 128, MTOK / 128), 256, GEMM_DSMEM>>>(
      h, wqkvT, nullptr, qkvh, MTOK, QKVDIM, DMODEL);

  // launch 5: attention with fused QK-norm (fp16 out)
  attn_kernel<<<NB * NS * NH, 256>>>(qkvh, qn, kn, o);

  // launch 6 (ncu -s 5 -c 1 target): x1 = x + o @ wo  (fp32 out)
  gemm_f16_kernel<float><<<dim3(DMODEL / 128, MTOK / 128), 256, GEMM_DSMEM>>>(
      o, woT, x, x1, MTOK, DMODEL, DMODEL);

  // launch 7: h2 = rmsnorm(x1) (fp16)
  rmsnorm_kernel<<<MTOK, 256>>>(x1, n2, h2);

  // launch 8: merged MLP up projection  [MTOK,4096] fp16
  gemm_f16_kernel<__half><<<dim3(HID2 / 128, MTOK / 128), 256, GEMM_DSMEM>>>(
      h2, w12T, nullptr, u12, MTOK, HID2, DMODEL);

  // launch 9: gate (fp16 out)
  swiglu_kernel<<<(MTOK * HIDDIM) / (256 * 4), 256>>>(u12, u1h);

  // launch 10: out = x1 + u1h @ w3  (fp32 out)
  gemm_f16_kernel<float><<<dim3(DMODEL / 128, MTOK / 128), 256, GEMM_DSMEM>>>(
      u1h, w3T, x1, out, MTOK, DMODEL, HIDDIM);
}